// round 1
// baseline (speedup 1.0000x reference)
#include <cuda_runtime.h>
#include <cuda_bf16.h>
#include <math.h>

// Problem constants
#define Bc 2
#define Tc 2048
#define Dc 1024
#define Hc 16
#define DHc 64
#define Rc 32
#define TDc (3*Dc)        // 3072
#define Mrows (Bc*Tc)     // 4096

// Scratch (device globals — no allocation allowed)
__device__ float g_qkv[(size_t)Bc*Tc*TDc];   // (B*T, 3D)   50 MB
__device__ float g_ql[(size_t)Bc*Hc*Tc*Rc];  // (B,H,T,R)    8 MB
__device__ float g_kl[(size_t)Bc*Hc*Tc*Rc];  //              8 MB
__device__ float g_y[(size_t)Bc*Tc*Dc];      // (B*T, D)    16 MB

// ---------------------------------------------------------------------------
// SGEMM: C[M,N] = A[M,K] @ B[K,N], all row-major, M%128==0, N%128==0, K%16==0
// 128x128 tile, BK=16, 256 threads, 8x8 per thread.
// ---------------------------------------------------------------------------
__device__ __forceinline__ void sgemm_body(const float* __restrict__ A,
                                           const float* __restrict__ B,
                                           float* __restrict__ C,
                                           int M, int N, int K) {
    __shared__ __align__(16) float As[16][128];
    __shared__ __align__(16) float Bs[16][128];
    const int tid = threadIdx.x;
    const int tr = tid >> 4;        // 0..15
    const int tc = tid & 15;        // 0..15
    const int brow = blockIdx.y, bcol = blockIdx.x;
    const float* Ab = A + (size_t)brow * 128 * K;
    const float* Bb = B + (size_t)bcol * 128;

    float acc[8][8];
#pragma unroll
    for (int i = 0; i < 8; i++)
#pragma unroll
        for (int j = 0; j < 8; j++) acc[i][j] = 0.f;

    const int aRow = tid >> 2;          // 0..63
    const int aCol = (tid & 3) << 2;    // 0,4,8,12
    const int bRow = tid >> 5;          // 0..7
    const int bCol = (tid & 31) << 2;   // 0..124

    for (int k0 = 0; k0 < K; k0 += 16) {
#pragma unroll
        for (int s = 0; s < 2; s++) {
            float4 av = *reinterpret_cast<const float4*>(&Ab[(size_t)(aRow + s*64) * K + k0 + aCol]);
            As[aCol+0][aRow + s*64] = av.x;
            As[aCol+1][aRow + s*64] = av.y;
            As[aCol+2][aRow + s*64] = av.z;
            As[aCol+3][aRow + s*64] = av.w;
            float4 bv = *reinterpret_cast<const float4*>(&Bb[(size_t)(k0 + bRow + s*8) * N + bCol]);
            *reinterpret_cast<float4*>(&Bs[bRow + s*8][bCol]) = bv;
        }
        __syncthreads();
#pragma unroll
        for (int k = 0; k < 16; k++) {
            float4 a0 = *reinterpret_cast<const float4*>(&As[k][tr*8]);
            float4 a1 = *reinterpret_cast<const float4*>(&As[k][tr*8+4]);
            float4 b0 = *reinterpret_cast<const float4*>(&Bs[k][tc*8]);
            float4 b1 = *reinterpret_cast<const float4*>(&Bs[k][tc*8+4]);
            float ra[8] = {a0.x,a0.y,a0.z,a0.w,a1.x,a1.y,a1.z,a1.w};
            float rb[8] = {b0.x,b0.y,b0.z,b0.w,b1.x,b1.y,b1.z,b1.w};
#pragma unroll
            for (int i = 0; i < 8; i++)
#pragma unroll
                for (int j = 0; j < 8; j++)
                    acc[i][j] = fmaf(ra[i], rb[j], acc[i][j]);
        }
        __syncthreads();
    }
#pragma unroll
    for (int i = 0; i < 8; i++) {
        const size_t row = (size_t)brow*128 + tr*8 + i;
#pragma unroll
        for (int j = 0; j < 8; j += 4) {
            float4 v = make_float4(acc[i][j], acc[i][j+1], acc[i][j+2], acc[i][j+3]);
            *reinterpret_cast<float4*>(&C[row * N + bcol*128 + tc*8 + j]) = v;
        }
    }
}

__global__ __launch_bounds__(256) void sgemm_qkv_kernel(const float* __restrict__ x,
                                                        const float* __restrict__ Wqkv) {
    sgemm_body(x, Wqkv, g_qkv, Mrows, TDc, Dc);
}

__global__ __launch_bounds__(256) void sgemm_out_kernel(const float* __restrict__ Wo,
                                                        float* __restrict__ out) {
    sgemm_body(g_y, Wo, out, Mrows, Dc, Dc);
}

// ---------------------------------------------------------------------------
// LSR projection: out[b,h,t,r] = (sum_d qkv[b,t,qoff+h*64+d] * W[h,d,r]) * core[h,r] * scale
// block = (b, h, 128-row t-tile), 256 threads.
// ---------------------------------------------------------------------------
__global__ __launch_bounds__(256) void lsr_kernel(int qoff,
                                                  const float* __restrict__ W,
                                                  const float* __restrict__ core,
                                                  float scale,
                                                  float* __restrict__ outp) {
    const int blk = blockIdx.x;
    const int tt = blk & 15;             // T/128 = 16
    const int h  = (blk >> 4) & 15;
    const int b  = blk >> 8;
    __shared__ __align__(16) float Ws[DHc*Rc];   // 2048
    __shared__ __align__(16) float qs[32*DHc];   // 2048
    __shared__ float cs[Rc];
    const int tid = threadIdx.x;
    const float* Wh = W + (size_t)h * DHc * Rc;
    for (int i = tid; i < DHc*Rc; i += 256) Ws[i] = Wh[i];
    if (tid < Rc) cs[tid] = core ? core[h*Rc + tid] : 1.0f;
    __syncthreads();
    for (int c = 0; c < 4; c++) {
        const int t0 = tt*128 + c*32;
        for (int i = tid; i < 32*DHc; i += 256) {
            const int tl = i >> 6, d = i & 63;
            qs[i] = g_qkv[((size_t)(b*Tc + t0 + tl)) * TDc + qoff + h*DHc + d];
        }
        __syncthreads();
        for (int e = tid; e < 32*Rc; e += 256) {
            const int tl = e >> 5, r = e & 31;
            float sum = 0.f;
#pragma unroll
            for (int d = 0; d < DHc; d++)
                sum = fmaf(qs[tl*DHc + d], Ws[d*Rc + r], sum);
            outp[((size_t)((b*Hc + h)*Tc + t0 + tl)) * Rc + r] = sum * cs[r] * scale;
        }
        __syncthreads();
    }
}

// ---------------------------------------------------------------------------
// Flash attention with low-rank scores.
// block = (b, h, 128-row q-tile); 128 threads, one thread per query row.
// ---------------------------------------------------------------------------
__global__ __launch_bounds__(128) void attn_kernel(float* __restrict__ y) {
    const int blk = blockIdx.x;
    const int qt = blk & 15;
    const int h  = (blk >> 4) & 15;
    const int b  = blk >> 8;
    const int t  = threadIdx.x;           // 0..127 query row in tile
    const int qi = qt*128 + t;

    __shared__ __align__(16) float kls[128*Rc];   // 16 KB
    __shared__ __align__(16) float vs[128*DHc];   // 32 KB

    float qlr[Rc];
    const float* qlrow = g_ql + ((size_t)((b*Hc + h)*Tc + qi)) * Rc;
#pragma unroll
    for (int r = 0; r < Rc; r += 4) {
        float4 v = *reinterpret_cast<const float4*>(&qlrow[r]);
        qlr[r] = v.x; qlr[r+1] = v.y; qlr[r+2] = v.z; qlr[r+3] = v.w;
    }
    float acc[DHc];
#pragma unroll
    for (int d = 0; d < DHc; d++) acc[d] = 0.f;
    float m = -1e30f, l = 0.f;

    const float* klbase = g_kl + ((size_t)((b*Hc + h)*Tc)) * Rc;
    const float* vbase  = g_qkv + (size_t)b*Tc*TDc + 2*Dc + h*DHc;

    for (int kt = 0; kt <= qt; kt++) {
        // cooperative loads: kl tile (1024 float4), v tile (2048 float4)
        const float4* klg = reinterpret_cast<const float4*>(klbase + (size_t)kt*128*Rc);
        float4* kls4 = reinterpret_cast<float4*>(kls);
#pragma unroll
        for (int i = 0; i < 8; i++) kls4[t + i*128] = klg[t + i*128];
#pragma unroll
        for (int i = 0; i < 16; i++) {
            const int f = t + i*128;
            const int j = f >> 4, d4 = f & 15;
            reinterpret_cast<float4*>(vs)[f] =
                *reinterpret_cast<const float4*>(vbase + (size_t)(kt*128 + j)*TDc + d4*4);
        }
        __syncthreads();

        const bool diag = (kt == qt);
        const int jmax = diag ? (t + 1) : 128;   // number of valid keys in tile
        for (int sub = 0; sub < 128; sub += 16) {
            if (sub >= jmax) break;
            float s[16];
            float tmax = -1e30f;
#pragma unroll
            for (int jj = 0; jj < 16; jj++) {
                const int j = sub + jj;
                float sv = 0.f;
                const float4* kr = reinterpret_cast<const float4*>(&kls[j*Rc]);
#pragma unroll
                for (int r4 = 0; r4 < Rc/4; r4++) {
                    float4 kv = kr[r4];
                    sv = fmaf(qlr[r4*4+0], kv.x, sv);
                    sv = fmaf(qlr[r4*4+1], kv.y, sv);
                    sv = fmaf(qlr[r4*4+2], kv.z, sv);
                    sv = fmaf(qlr[r4*4+3], kv.w, sv);
                }
                sv = (j < jmax) ? sv : -1e30f;
                s[jj] = sv;
                tmax = fmaxf(tmax, sv);
            }
            if (tmax > m) {
                const float corr = __expf(m - tmax);
                l *= corr;
#pragma unroll
                for (int d = 0; d < DHc; d++) acc[d] *= corr;
                m = tmax;
            }
#pragma unroll
            for (int jj = 0; jj < 16; jj++) {
                const int j = sub + jj;
                const float p = __expf(s[jj] - m);
                l += p;
                const float4* vr = reinterpret_cast<const float4*>(&vs[j*DHc]);
#pragma unroll
                for (int d4 = 0; d4 < DHc/4; d4++) {
                    float4 vv = vr[d4];
                    acc[d4*4+0] = fmaf(p, vv.x, acc[d4*4+0]);
                    acc[d4*4+1] = fmaf(p, vv.y, acc[d4*4+1]);
                    acc[d4*4+2] = fmaf(p, vv.z, acc[d4*4+2]);
                    acc[d4*4+3] = fmaf(p, vv.w, acc[d4*4+3]);
                }
            }
        }
        __syncthreads();
    }

    const float inv = 1.f / l;
    float* yrow = y + ((size_t)(b*Tc + qi)) * Dc + h*DHc;
#pragma unroll
    for (int d = 0; d < DHc; d += 4) {
        float4 v = make_float4(acc[d]*inv, acc[d+1]*inv, acc[d+2]*inv, acc[d+3]*inv);
        *reinterpret_cast<float4*>(&yrow[d]) = v;
    }
}

// Helper kernel-free device-global Y access: attention writes to g_y.
__global__ __launch_bounds__(128) void attn_entry_kernel_unused() {}

extern "C" void kernel_launch(void* const* d_in, const int* in_sizes, int n_in,
                              void* d_out, int out_size) {
    const float* x      = (const float*)d_in[0];
    const float* W_qkv  = (const float*)d_in[1];
    const float* W_qlsr = (const float*)d_in[2];
    const float* W_klsr = (const float*)d_in[3];
    const float* core   = (const float*)d_in[4];
    const float* W_o    = (const float*)d_in[5];
    float* out = (float*)d_out;

    float* d_ql; cudaGetSymbolAddress((void**)&d_ql, g_ql);
    float* d_kl; cudaGetSymbolAddress((void**)&d_kl, g_kl);
    float* d_y;  cudaGetSymbolAddress((void**)&d_y,  g_y);

    // 1) qkv = x @ W_qkv  (4096 x 3072 x 1024)
    sgemm_qkv_kernel<<<dim3(TDc/128, Mrows/128), 256>>>(x, W_qkv);

    // 2) low-rank projections (core and 1/sqrt(R) folded into ql)
    const float scale = 0.17677669529663687f;  // 1/sqrt(32)
    lsr_kernel<<<Bc*Hc*(Tc/128), 256>>>(0,   W_qlsr, core,   scale, d_ql);
    lsr_kernel<<<Bc*Hc*(Tc/128), 256>>>(Dc,  W_klsr, nullptr, 1.0f, d_kl);

    // 3) causal flash attention -> g_y  (B*T, D)
    attn_kernel<<<Bc*Hc*(Tc/128), 128>>>(d_y);

    // 4) out = y @ W_o  (4096 x 1024 x 1024)
    sgemm_out_kernel<<<dim3(Dc/128, Mrows/128), 256>>>(W_o, out);
}

// round 2
// speedup vs baseline: 1.4703x; 1.4703x over previous
#include <cuda_runtime.h>
#include <cuda_bf16.h>
#include <math.h>

// Problem constants
#define Bc 2
#define Tc 2048
#define Dc 1024
#define Hc 16
#define DHc 64
#define Rc 32
#define TDc (3*Dc)        // 3072
#define Mrows (Bc*Tc)     // 4096

// Scratch (device globals — no allocation allowed)
__device__ float g_qkv[(size_t)Bc*Tc*TDc];   // (B*T, 3D)
__device__ float g_ql[(size_t)Bc*Hc*Tc*Rc];  // (B,H,T,R)
__device__ float g_kl[(size_t)Bc*Hc*Tc*Rc];
__device__ float g_y[(size_t)Bc*Tc*Dc];      // (B*T, D)

// ---------------------------------------------------------------------------
// TF32 tensor-core GEMM: C[M,N] = A[M,K] @ B[K,N], row-major.
// 128x128 block tile, BK=16 double-buffered, 256 threads (8 warps),
// warp tile 64x32 via mma.sync.m16n8k8 tf32.
// M%128==0, N%128==0, K%16==0.
// ---------------------------------------------------------------------------
__device__ __forceinline__ float cvt_tf32(float x) {
    float r;
    asm("cvt.rna.tf32.f32 %0, %1;" : "=f"(r) : "f"(x));
    return r;
}

__device__ __forceinline__ void mma_tf32(float* c, const unsigned* a, const unsigned* b) {
    asm volatile(
        "mma.sync.aligned.m16n8k8.row.col.f32.tf32.tf32.f32 "
        "{%0,%1,%2,%3},{%4,%5,%6,%7},{%8,%9},{%0,%1,%2,%3};"
        : "+f"(c[0]), "+f"(c[1]), "+f"(c[2]), "+f"(c[3])
        : "r"(a[0]), "r"(a[1]), "r"(a[2]), "r"(a[3]), "r"(b[0]), "r"(b[1]));
}

__global__ __launch_bounds__(256) void gemm_tf32_kernel(const float* __restrict__ A,
                                                        const float* __restrict__ B,
                                                        float* __restrict__ C,
                                                        int M, int N, int K) {
    __shared__ float As[2][128][20];   // [m][k] pad 4 -> stride 20
    __shared__ float Bs[2][16][136];   // [k][n] pad 8 -> stride 136

    const int tid = threadIdx.x;
    const int warp = tid >> 5, lane = tid & 31;
    const int g = lane >> 2, tig = lane & 3;
    const int wm = warp >> 2;          // 0..1
    const int wn = warp & 3;           // 0..3

    // global load indexing: 2 float4 each for A and B per stage
    const int fa0 = tid * 2;
    const int aRow0 = fa0 >> 2,       aKc0 = (fa0 & 3) << 2;
    const int aRow1 = (fa0+1) >> 2,   aKc1 = ((fa0+1) & 3) << 2;
    const int bKr0 = fa0 >> 5,        bNc0 = (fa0 & 31) << 2;
    const int bKr1 = (fa0+1) >> 5,    bNc1 = ((fa0+1) & 31) << 2;

    const float* Ab = A + (size_t)blockIdx.y * 128 * K;
    const float* Bb = B + (size_t)blockIdx.x * 128;

    float acc[4][4][4];
#pragma unroll
    for (int i = 0; i < 4; i++)
#pragma unroll
        for (int j = 0; j < 4; j++)
#pragma unroll
            for (int e = 0; e < 4; e++) acc[i][j][e] = 0.f;

    const int nK = K >> 4;

    // prologue: stage 0
    {
        float4 av0 = *reinterpret_cast<const float4*>(&Ab[(size_t)aRow0 * K + aKc0]);
        float4 av1 = *reinterpret_cast<const float4*>(&Ab[(size_t)aRow1 * K + aKc1]);
        float4 bv0 = *reinterpret_cast<const float4*>(&Bb[(size_t)bKr0 * N + bNc0]);
        float4 bv1 = *reinterpret_cast<const float4*>(&Bb[(size_t)bKr1 * N + bNc1]);
        As[0][aRow0][aKc0+0] = cvt_tf32(av0.x); As[0][aRow0][aKc0+1] = cvt_tf32(av0.y);
        As[0][aRow0][aKc0+2] = cvt_tf32(av0.z); As[0][aRow0][aKc0+3] = cvt_tf32(av0.w);
        As[0][aRow1][aKc1+0] = cvt_tf32(av1.x); As[0][aRow1][aKc1+1] = cvt_tf32(av1.y);
        As[0][aRow1][aKc1+2] = cvt_tf32(av1.z); As[0][aRow1][aKc1+3] = cvt_tf32(av1.w);
        float4 c0 = make_float4(cvt_tf32(bv0.x), cvt_tf32(bv0.y), cvt_tf32(bv0.z), cvt_tf32(bv0.w));
        float4 c1 = make_float4(cvt_tf32(bv1.x), cvt_tf32(bv1.y), cvt_tf32(bv1.z), cvt_tf32(bv1.w));
        *reinterpret_cast<float4*>(&Bs[0][bKr0][bNc0]) = c0;
        *reinterpret_cast<float4*>(&Bs[0][bKr1][bNc1]) = c1;
    }
    __syncthreads();

    int buf = 0;
    for (int kt = 0; kt < nK; kt++) {
        float4 na0, na1, nb0, nb1;
        const bool more = (kt + 1 < nK);
        if (more) {
            const int k0 = (kt + 1) << 4;
            na0 = *reinterpret_cast<const float4*>(&Ab[(size_t)aRow0 * K + k0 + aKc0]);
            na1 = *reinterpret_cast<const float4*>(&Ab[(size_t)aRow1 * K + k0 + aKc1]);
            nb0 = *reinterpret_cast<const float4*>(&Bb[(size_t)(k0 + bKr0) * N + bNc0]);
            nb1 = *reinterpret_cast<const float4*>(&Bb[(size_t)(k0 + bKr1) * N + bNc1]);
        }

#pragma unroll
        for (int ks = 0; ks < 16; ks += 8) {
            unsigned afr[4][4], bfr[4][2];
#pragma unroll
            for (int im = 0; im < 4; im++) {
                const int m0 = wm * 64 + im * 16;
                afr[im][0] = __float_as_uint(As[buf][m0 + g     ][ks + tig    ]);
                afr[im][1] = __float_as_uint(As[buf][m0 + g + 8 ][ks + tig    ]);
                afr[im][2] = __float_as_uint(As[buf][m0 + g     ][ks + tig + 4]);
                afr[im][3] = __float_as_uint(As[buf][m0 + g + 8 ][ks + tig + 4]);
            }
#pragma unroll
            for (int in_ = 0; in_ < 4; in_++) {
                const int n0 = wn * 32 + in_ * 8;
                bfr[in_][0] = __float_as_uint(Bs[buf][ks + tig    ][n0 + g]);
                bfr[in_][1] = __float_as_uint(Bs[buf][ks + tig + 4][n0 + g]);
            }
#pragma unroll
            for (int im = 0; im < 4; im++)
#pragma unroll
                for (int in_ = 0; in_ < 4; in_++)
                    mma_tf32(acc[im][in_], afr[im], bfr[in_]);
        }

        if (more) {
            const int nb = buf ^ 1;
            As[nb][aRow0][aKc0+0] = cvt_tf32(na0.x); As[nb][aRow0][aKc0+1] = cvt_tf32(na0.y);
            As[nb][aRow0][aKc0+2] = cvt_tf32(na0.z); As[nb][aRow0][aKc0+3] = cvt_tf32(na0.w);
            As[nb][aRow1][aKc1+0] = cvt_tf32(na1.x); As[nb][aRow1][aKc1+1] = cvt_tf32(na1.y);
            As[nb][aRow1][aKc1+2] = cvt_tf32(na1.z); As[nb][aRow1][aKc1+3] = cvt_tf32(na1.w);
            float4 c0 = make_float4(cvt_tf32(nb0.x), cvt_tf32(nb0.y), cvt_tf32(nb0.z), cvt_tf32(nb0.w));
            float4 c1 = make_float4(cvt_tf32(nb1.x), cvt_tf32(nb1.y), cvt_tf32(nb1.z), cvt_tf32(nb1.w));
            *reinterpret_cast<float4*>(&Bs[nb][bKr0][bNc0]) = c0;
            *reinterpret_cast<float4*>(&Bs[nb][bKr1][bNc1]) = c1;
            __syncthreads();
            buf ^= 1;
        }
    }

    // epilogue
#pragma unroll
    for (int im = 0; im < 4; im++) {
        const size_t row0 = (size_t)blockIdx.y * 128 + wm * 64 + im * 16 + g;
#pragma unroll
        for (int in_ = 0; in_ < 4; in_++) {
            const size_t col = (size_t)blockIdx.x * 128 + wn * 32 + in_ * 8 + tig * 2;
            float2 v0 = make_float2(acc[im][in_][0], acc[im][in_][1]);
            float2 v1 = make_float2(acc[im][in_][2], acc[im][in_][3]);
            *reinterpret_cast<float2*>(&C[row0 * N + col])       = v0;
            *reinterpret_cast<float2*>(&C[(row0 + 8) * N + col]) = v1;
        }
    }
}

// ---------------------------------------------------------------------------
// LSR projection: out[b,h,t,r] = (sum_d qkv[b,t,qoff+h*64+d] * W[h,d,r]) * core[h,r] * scale
// ---------------------------------------------------------------------------
__global__ __launch_bounds__(256) void lsr_kernel(int qoff,
                                                  const float* __restrict__ W,
                                                  const float* __restrict__ core,
                                                  float scale,
                                                  float* __restrict__ outp) {
    const int blk = blockIdx.x;
    const int tt = blk & 15;
    const int h  = (blk >> 4) & 15;
    const int b  = blk >> 8;
    __shared__ __align__(16) float Ws[DHc*Rc];
    __shared__ __align__(16) float qs[32*DHc];
    __shared__ float cs[Rc];
    const int tid = threadIdx.x;
    const float* Wh = W + (size_t)h * DHc * Rc;
    for (int i = tid; i < DHc*Rc; i += 256) Ws[i] = Wh[i];
    if (tid < Rc) cs[tid] = core ? core[h*Rc + tid] : 1.0f;
    __syncthreads();
    for (int c = 0; c < 4; c++) {
        const int t0 = tt*128 + c*32;
        for (int i = tid; i < 32*DHc; i += 256) {
            const int tl = i >> 6, d = i & 63;
            qs[i] = g_qkv[((size_t)(b*Tc + t0 + tl)) * TDc + qoff + h*DHc + d];
        }
        __syncthreads();
        for (int e = tid; e < 32*Rc; e += 256) {
            const int tl = e >> 5, r = e & 31;
            float sum = 0.f;
#pragma unroll
            for (int d = 0; d < DHc; d++)
                sum = fmaf(qs[tl*DHc + d], Ws[d*Rc + r], sum);
            outp[((size_t)((b*Hc + h)*Tc + t0 + tl)) * Rc + r] = sum * cs[r] * scale;
        }
        __syncthreads();
    }
}

// ---------------------------------------------------------------------------
// Flash attention with low-rank scores (unchanged from R1).
// block = (b, h, 128-row q-tile); 128 threads, one thread per query row.
// ---------------------------------------------------------------------------
__global__ __launch_bounds__(128) void attn_kernel(float* __restrict__ y) {
    const int blk = blockIdx.x;
    const int qt = blk & 15;
    const int h  = (blk >> 4) & 15;
    const int b  = blk >> 8;
    const int t  = threadIdx.x;
    const int qi = qt*128 + t;

    __shared__ __align__(16) float kls[128*Rc];
    __shared__ __align__(16) float vs[128*DHc];

    float qlr[Rc];
    const float* qlrow = g_ql + ((size_t)((b*Hc + h)*Tc + qi)) * Rc;
#pragma unroll
    for (int r = 0; r < Rc; r += 4) {
        float4 v = *reinterpret_cast<const float4*>(&qlrow[r]);
        qlr[r] = v.x; qlr[r+1] = v.y; qlr[r+2] = v.z; qlr[r+3] = v.w;
    }
    float acc[DHc];
#pragma unroll
    for (int d = 0; d < DHc; d++) acc[d] = 0.f;
    float m = -1e30f, l = 0.f;

    const float* klbase = g_kl + ((size_t)((b*Hc + h)*Tc)) * Rc;
    const float* vbase  = g_qkv + (size_t)b*Tc*TDc + 2*Dc + h*DHc;

    for (int kt = 0; kt <= qt; kt++) {
        const float4* klg = reinterpret_cast<const float4*>(klbase + (size_t)kt*128*Rc);
        float4* kls4 = reinterpret_cast<float4*>(kls);
#pragma unroll
        for (int i = 0; i < 8; i++) kls4[t + i*128] = klg[t + i*128];
#pragma unroll
        for (int i = 0; i < 16; i++) {
            const int f = t + i*128;
            const int j = f >> 4, d4 = f & 15;
            reinterpret_cast<float4*>(vs)[f] =
                *reinterpret_cast<const float4*>(vbase + (size_t)(kt*128 + j)*TDc + d4*4);
        }
        __syncthreads();

        const bool diag = (kt == qt);
        const int jmax = diag ? (t + 1) : 128;
        for (int sub = 0; sub < 128; sub += 16) {
            if (sub >= jmax) break;
            float s[16];
            float tmax = -1e30f;
#pragma unroll
            for (int jj = 0; jj < 16; jj++) {
                const int j = sub + jj;
                float sv = 0.f;
                const float4* kr = reinterpret_cast<const float4*>(&kls[j*Rc]);
#pragma unroll
                for (int r4 = 0; r4 < Rc/4; r4++) {
                    float4 kv = kr[r4];
                    sv = fmaf(qlr[r4*4+0], kv.x, sv);
                    sv = fmaf(qlr[r4*4+1], kv.y, sv);
                    sv = fmaf(qlr[r4*4+2], kv.z, sv);
                    sv = fmaf(qlr[r4*4+3], kv.w, sv);
                }
                sv = (j < jmax) ? sv : -1e30f;
                s[jj] = sv;
                tmax = fmaxf(tmax, sv);
            }
            if (tmax > m) {
                const float corr = __expf(m - tmax);
                l *= corr;
#pragma unroll
                for (int d = 0; d < DHc; d++) acc[d] *= corr;
                m = tmax;
            }
#pragma unroll
            for (int jj = 0; jj < 16; jj++) {
                const int j = sub + jj;
                const float p = __expf(s[jj] - m);
                l += p;
                const float4* vr = reinterpret_cast<const float4*>(&vs[j*DHc]);
#pragma unroll
                for (int d4 = 0; d4 < DHc/4; d4++) {
                    float4 vv = vr[d4];
                    acc[d4*4+0] = fmaf(p, vv.x, acc[d4*4+0]);
                    acc[d4*4+1] = fmaf(p, vv.y, acc[d4*4+1]);
                    acc[d4*4+2] = fmaf(p, vv.z, acc[d4*4+2]);
                    acc[d4*4+3] = fmaf(p, vv.w, acc[d4*4+3]);
                }
            }
        }
        __syncthreads();
    }

    const float inv = 1.f / l;
    float* yrow = y + ((size_t)(b*Tc + qi)) * Dc + h*DHc;
#pragma unroll
    for (int d = 0; d < DHc; d += 4) {
        float4 v = make_float4(acc[d]*inv, acc[d+1]*inv, acc[d+2]*inv, acc[d+3]*inv);
        *reinterpret_cast<float4*>(&yrow[d]) = v;
    }
}

extern "C" void kernel_launch(void* const* d_in, const int* in_sizes, int n_in,
                              void* d_out, int out_size) {
    const float* x      = (const float*)d_in[0];
    const float* W_qkv  = (const float*)d_in[1];
    const float* W_qlsr = (const float*)d_in[2];
    const float* W_klsr = (const float*)d_in[3];
    const float* core   = (const float*)d_in[4];
    const float* W_o    = (const float*)d_in[5];
    float* out = (float*)d_out;

    float* d_qkv; cudaGetSymbolAddress((void**)&d_qkv, g_qkv);
    float* d_ql;  cudaGetSymbolAddress((void**)&d_ql,  g_ql);
    float* d_kl;  cudaGetSymbolAddress((void**)&d_kl,  g_kl);
    float* d_y;   cudaGetSymbolAddress((void**)&d_y,   g_y);

    // 1) qkv = x @ W_qkv  (4096 x 3072 x 1024), tf32 tensor cores
    gemm_tf32_kernel<<<dim3(TDc/128, Mrows/128), 256>>>(x, W_qkv, d_qkv, Mrows, TDc, Dc);

    // 2) low-rank projections (core and 1/sqrt(R) folded into ql)
    const float scale = 0.17677669529663687f;  // 1/sqrt(32)
    lsr_kernel<<<Bc*Hc*(Tc/128), 256>>>(0,   W_qlsr, core,   scale, d_ql);
    lsr_kernel<<<Bc*Hc*(Tc/128), 256>>>(Dc,  W_klsr, nullptr, 1.0f, d_kl);

    // 3) causal flash attention -> g_y  (B*T, D)
    attn_kernel<<<Bc*Hc*(Tc/128), 128>>>(d_y);

    // 4) out = y @ W_o  (4096 x 1024 x 1024), tf32 tensor cores
    gemm_tf32_kernel<<<dim3(Dc/128, Mrows/128), 256>>>(d_y, W_o, out, Mrows, Dc, Dc);
}

// round 3
// speedup vs baseline: 2.4178x; 1.6445x over previous
#include <cuda_runtime.h>
#include <cuda_bf16.h>
#include <math.h>

// Problem constants
#define Bc 2
#define Tc 2048
#define Dc 1024
#define Hc 16
#define DHc 64
#define Rc 32
#define TDc (3*Dc)        // 3072
#define Mrows (Bc*Tc)     // 4096

// Scratch (device globals — no allocation allowed)
__device__ float g_qkv[(size_t)Bc*Tc*TDc];   // (B*T, 3D)
__device__ float g_ql[(size_t)Bc*Hc*Tc*Rc];  // (B,H,T,R)
__device__ float g_kl[(size_t)Bc*Hc*Tc*Rc];
__device__ float g_y[(size_t)Bc*Tc*Dc];      // (B*T, D)

__device__ __forceinline__ float cvt_tf32(float x) {
    float r;
    asm("cvt.rna.tf32.f32 %0, %1;" : "=f"(r) : "f"(x));
    return r;
}

__device__ __forceinline__ void mma_tf32(float* c, const unsigned* a, const unsigned* b) {
    asm volatile(
        "mma.sync.aligned.m16n8k8.row.col.f32.tf32.tf32.f32 "
        "{%0,%1,%2,%3},{%4,%5,%6,%7},{%8,%9},{%0,%1,%2,%3};"
        : "+f"(c[0]), "+f"(c[1]), "+f"(c[2]), "+f"(c[3])
        : "r"(a[0]), "r"(a[1]), "r"(a[2]), "r"(a[3]), "r"(b[0]), "r"(b[1]));
}

// ---------------------------------------------------------------------------
// TF32 tensor-core GEMM: C[M,N] = A[M,K] @ B[K,N], row-major. (unchanged R2)
// ---------------------------------------------------------------------------
__global__ __launch_bounds__(256) void gemm_tf32_kernel(const float* __restrict__ A,
                                                        const float* __restrict__ B,
                                                        float* __restrict__ C,
                                                        int M, int N, int K) {
    __shared__ float As[2][128][20];
    __shared__ float Bs[2][16][136];

    const int tid = threadIdx.x;
    const int warp = tid >> 5, lane = tid & 31;
    const int g = lane >> 2, tig = lane & 3;
    const int wm = warp >> 2;
    const int wn = warp & 3;

    const int fa0 = tid * 2;
    const int aRow0 = fa0 >> 2,       aKc0 = (fa0 & 3) << 2;
    const int aRow1 = (fa0+1) >> 2,   aKc1 = ((fa0+1) & 3) << 2;
    const int bKr0 = fa0 >> 5,        bNc0 = (fa0 & 31) << 2;
    const int bKr1 = (fa0+1) >> 5,    bNc1 = ((fa0+1) & 31) << 2;

    const float* Ab = A + (size_t)blockIdx.y * 128 * K;
    const float* Bb = B + (size_t)blockIdx.x * 128;

    float acc[4][4][4];
#pragma unroll
    for (int i = 0; i < 4; i++)
#pragma unroll
        for (int j = 0; j < 4; j++)
#pragma unroll
            for (int e = 0; e < 4; e++) acc[i][j][e] = 0.f;

    const int nK = K >> 4;

    {
        float4 av0 = *reinterpret_cast<const float4*>(&Ab[(size_t)aRow0 * K + aKc0]);
        float4 av1 = *reinterpret_cast<const float4*>(&Ab[(size_t)aRow1 * K + aKc1]);
        float4 bv0 = *reinterpret_cast<const float4*>(&Bb[(size_t)bKr0 * N + bNc0]);
        float4 bv1 = *reinterpret_cast<const float4*>(&Bb[(size_t)bKr1 * N + bNc1]);
        As[0][aRow0][aKc0+0] = cvt_tf32(av0.x); As[0][aRow0][aKc0+1] = cvt_tf32(av0.y);
        As[0][aRow0][aKc0+2] = cvt_tf32(av0.z); As[0][aRow0][aKc0+3] = cvt_tf32(av0.w);
        As[0][aRow1][aKc1+0] = cvt_tf32(av1.x); As[0][aRow1][aKc1+1] = cvt_tf32(av1.y);
        As[0][aRow1][aKc1+2] = cvt_tf32(av1.z); As[0][aRow1][aKc1+3] = cvt_tf32(av1.w);
        float4 c0 = make_float4(cvt_tf32(bv0.x), cvt_tf32(bv0.y), cvt_tf32(bv0.z), cvt_tf32(bv0.w));
        float4 c1 = make_float4(cvt_tf32(bv1.x), cvt_tf32(bv1.y), cvt_tf32(bv1.z), cvt_tf32(bv1.w));
        *reinterpret_cast<float4*>(&Bs[0][bKr0][bNc0]) = c0;
        *reinterpret_cast<float4*>(&Bs[0][bKr1][bNc1]) = c1;
    }
    __syncthreads();

    int buf = 0;
    for (int kt = 0; kt < nK; kt++) {
        float4 na0, na1, nb0, nb1;
        const bool more = (kt + 1 < nK);
        if (more) {
            const int k0 = (kt + 1) << 4;
            na0 = *reinterpret_cast<const float4*>(&Ab[(size_t)aRow0 * K + k0 + aKc0]);
            na1 = *reinterpret_cast<const float4*>(&Ab[(size_t)aRow1 * K + k0 + aKc1]);
            nb0 = *reinterpret_cast<const float4*>(&Bb[(size_t)(k0 + bKr0) * N + bNc0]);
            nb1 = *reinterpret_cast<const float4*>(&Bb[(size_t)(k0 + bKr1) * N + bNc1]);
        }

#pragma unroll
        for (int ks = 0; ks < 16; ks += 8) {
            unsigned afr[4][4], bfr[4][2];
#pragma unroll
            for (int im = 0; im < 4; im++) {
                const int m0 = wm * 64 + im * 16;
                afr[im][0] = __float_as_uint(As[buf][m0 + g     ][ks + tig    ]);
                afr[im][1] = __float_as_uint(As[buf][m0 + g + 8 ][ks + tig    ]);
                afr[im][2] = __float_as_uint(As[buf][m0 + g     ][ks + tig + 4]);
                afr[im][3] = __float_as_uint(As[buf][m0 + g + 8 ][ks + tig + 4]);
            }
#pragma unroll
            for (int in_ = 0; in_ < 4; in_++) {
                const int n0 = wn * 32 + in_ * 8;
                bfr[in_][0] = __float_as_uint(Bs[buf][ks + tig    ][n0 + g]);
                bfr[in_][1] = __float_as_uint(Bs[buf][ks + tig + 4][n0 + g]);
            }
#pragma unroll
            for (int im = 0; im < 4; im++)
#pragma unroll
                for (int in_ = 0; in_ < 4; in_++)
                    mma_tf32(acc[im][in_], afr[im], bfr[in_]);
        }

        if (more) {
            const int nb = buf ^ 1;
            As[nb][aRow0][aKc0+0] = cvt_tf32(na0.x); As[nb][aRow0][aKc0+1] = cvt_tf32(na0.y);
            As[nb][aRow0][aKc0+2] = cvt_tf32(na0.z); As[nb][aRow0][aKc0+3] = cvt_tf32(na0.w);
            As[nb][aRow1][aKc1+0] = cvt_tf32(na1.x); As[nb][aRow1][aKc1+1] = cvt_tf32(na1.y);
            As[nb][aRow1][aKc1+2] = cvt_tf32(na1.z); As[nb][aRow1][aKc1+3] = cvt_tf32(na1.w);
            float4 c0 = make_float4(cvt_tf32(nb0.x), cvt_tf32(nb0.y), cvt_tf32(nb0.z), cvt_tf32(nb0.w));
            float4 c1 = make_float4(cvt_tf32(nb1.x), cvt_tf32(nb1.y), cvt_tf32(nb1.z), cvt_tf32(nb1.w));
            *reinterpret_cast<float4*>(&Bs[nb][bKr0][bNc0]) = c0;
            *reinterpret_cast<float4*>(&Bs[nb][bKr1][bNc1]) = c1;
            __syncthreads();
            buf ^= 1;
        }
    }

#pragma unroll
    for (int im = 0; im < 4; im++) {
        const size_t row0 = (size_t)blockIdx.y * 128 + wm * 64 + im * 16 + g;
#pragma unroll
        for (int in_ = 0; in_ < 4; in_++) {
            const size_t col = (size_t)blockIdx.x * 128 + wn * 32 + in_ * 8 + tig * 2;
            float2 v0 = make_float2(acc[im][in_][0], acc[im][in_][1]);
            float2 v1 = make_float2(acc[im][in_][2], acc[im][in_][3]);
            *reinterpret_cast<float2*>(&C[row0 * N + col])       = v0;
            *reinterpret_cast<float2*>(&C[(row0 + 8) * N + col]) = v1;
        }
    }
}

// ---------------------------------------------------------------------------
// LSR projection (unchanged)
// ---------------------------------------------------------------------------
__global__ __launch_bounds__(256) void lsr_kernel(int qoff,
                                                  const float* __restrict__ W,
                                                  const float* __restrict__ core,
                                                  float scale,
                                                  float* __restrict__ outp) {
    const int blk = blockIdx.x;
    const int tt = blk & 15;
    const int h  = (blk >> 4) & 15;
    const int b  = blk >> 8;
    __shared__ __align__(16) float Ws[DHc*Rc];
    __shared__ __align__(16) float qs[32*DHc];
    __shared__ float cs[Rc];
    const int tid = threadIdx.x;
    const float* Wh = W + (size_t)h * DHc * Rc;
    for (int i = tid; i < DHc*Rc; i += 256) Ws[i] = Wh[i];
    if (tid < Rc) cs[tid] = core ? core[h*Rc + tid] : 1.0f;
    __syncthreads();
    for (int c = 0; c < 4; c++) {
        const int t0 = tt*128 + c*32;
        for (int i = tid; i < 32*DHc; i += 256) {
            const int tl = i >> 6, d = i & 63;
            qs[i] = g_qkv[((size_t)(b*Tc + t0 + tl)) * TDc + qoff + h*DHc + d];
        }
        __syncthreads();
        for (int e = tid; e < 32*Rc; e += 256) {
            const int tl = e >> 5, r = e & 31;
            float sum = 0.f;
#pragma unroll
            for (int d = 0; d < DHc; d++)
                sum = fmaf(qs[tl*DHc + d], Ws[d*Rc + r], sum);
            outp[((size_t)((b*Hc + h)*Tc + t0 + tl)) * Rc + r] = sum * cs[r] * scale;
        }
        __syncthreads();
    }
}

// ---------------------------------------------------------------------------
// Tensor-core flash attention (tf32 mma).
// Block = (b, h, 128-row q-tile); 256 threads (8 warps), warp = 16 q-rows.
// kls[128][36] (bank: 4g+tig distinct), vs[128][72] (bank: 8tig+g distinct).
// ---------------------------------------------------------------------------
#define KLS_STRIDE 36
#define VS_STRIDE  72
#define ATTN_SMEM ((128*KLS_STRIDE + 128*VS_STRIDE) * 4)

__global__ __launch_bounds__(256) void attn_tc_kernel(float* __restrict__ y) {
    extern __shared__ float sm[];
    float* kls = sm;                    // [128][36]
    float* vs  = sm + 128*KLS_STRIDE;   // [128][72]

    const int blk = blockIdx.x;
    const int qt = blk & 15;
    const int h  = (blk >> 4) & 15;
    const int b  = blk >> 8;
    const int tid  = threadIdx.x;
    const int warp = tid >> 5, lane = tid & 31;
    const int g = lane >> 2, tig = lane & 3;
    const int m0 = warp * 16;

    // Preload ql A-fragments (scale+core already folded into g_ql)
    unsigned aq[4][4];
    {
        const float* qlp = g_ql + ((size_t)((b*Hc + h)*Tc + qt*128 + m0)) * Rc;
#pragma unroll
        for (int ks = 0; ks < 4; ks++) {
            aq[ks][0] = __float_as_uint(cvt_tf32(qlp[(size_t)(g    )*Rc + ks*8 + tig    ]));
            aq[ks][1] = __float_as_uint(cvt_tf32(qlp[(size_t)(g + 8)*Rc + ks*8 + tig    ]));
            aq[ks][2] = __float_as_uint(cvt_tf32(qlp[(size_t)(g    )*Rc + ks*8 + tig + 4]));
            aq[ks][3] = __float_as_uint(cvt_tf32(qlp[(size_t)(g + 8)*Rc + ks*8 + tig + 4]));
        }
    }

    float of[8][4];
#pragma unroll
    for (int nt = 0; nt < 8; nt++)
#pragma unroll
        for (int e = 0; e < 4; e++) of[nt][e] = 0.f;
    float m0r = -1e30f, m1r = -1e30f, l0 = 0.f, l1 = 0.f;

    const float* klg = g_kl + ((size_t)((b*Hc + h)*Tc)) * Rc;
    const float* vg  = g_qkv + (size_t)b*Tc*TDc + 2*Dc + h*DHc;

    const unsigned srcA = (lane & ~3u) | (unsigned)(tig >> 1);
    const unsigned srcB = srcA + 2u;

    for (int kt = 0; kt <= qt; kt++) {
        if (kt) __syncthreads();
        // cooperative loads (with tf32 rounding)
#pragma unroll
        for (int i = 0; i < 4; i++) {
            const int f = tid + i*256;
            const int key = f >> 3, r0 = (f & 7) << 2;
            float4 v = *reinterpret_cast<const float4*>(klg + (size_t)(kt*128 + key)*Rc + r0);
            float* dst = kls + key*KLS_STRIDE + r0;
            dst[0] = cvt_tf32(v.x); dst[1] = cvt_tf32(v.y);
            dst[2] = cvt_tf32(v.z); dst[3] = cvt_tf32(v.w);
        }
#pragma unroll
        for (int i = 0; i < 8; i++) {
            const int f = tid + i*256;
            const int key = f >> 4, j = (f & 15) << 2;
            float4 v = *reinterpret_cast<const float4*>(vg + (size_t)(kt*128 + key)*TDc + j);
            float* dst = vs + key*VS_STRIDE + j;
            dst[0] = cvt_tf32(v.x); dst[1] = cvt_tf32(v.y);
            dst[2] = cvt_tf32(v.z); dst[3] = cvt_tf32(v.w);
        }
        __syncthreads();

        // S = ql @ kl^T  (16 x 128)
        float sf[16][4];
#pragma unroll
        for (int nt = 0; nt < 16; nt++) {
#pragma unroll
            for (int e = 0; e < 4; e++) sf[nt][e] = 0.f;
#pragma unroll
            for (int ks = 0; ks < 4; ks++) {
                unsigned bb[2];
                bb[0] = __float_as_uint(kls[(nt*8 + g)*KLS_STRIDE + ks*8 + tig    ]);
                bb[1] = __float_as_uint(kls[(nt*8 + g)*KLS_STRIDE + ks*8 + tig + 4]);
                mma_tf32(sf[nt], aq[ks], bb);
            }
        }

        // causal mask on diagonal tile (local col > local row)
        if (kt == qt) {
            const int r0l = m0 + g, r1l = r0l + 8;
#pragma unroll
            for (int nt = 0; nt < 16; nt++) {
                const int c = nt*8 + 2*tig;
                if (c     > r0l) sf[nt][0] = -1e30f;
                if (c + 1 > r0l) sf[nt][1] = -1e30f;
                if (c     > r1l) sf[nt][2] = -1e30f;
                if (c + 1 > r1l) sf[nt][3] = -1e30f;
            }
        }

        // row max (per-thread then quad reduce)
        float mx0 = -1e30f, mx1 = -1e30f;
#pragma unroll
        for (int nt = 0; nt < 16; nt++) {
            mx0 = fmaxf(mx0, fmaxf(sf[nt][0], sf[nt][1]));
            mx1 = fmaxf(mx1, fmaxf(sf[nt][2], sf[nt][3]));
        }
        mx0 = fmaxf(mx0, __shfl_xor_sync(0xffffffffu, mx0, 1));
        mx0 = fmaxf(mx0, __shfl_xor_sync(0xffffffffu, mx0, 2));
        mx1 = fmaxf(mx1, __shfl_xor_sync(0xffffffffu, mx1, 1));
        mx1 = fmaxf(mx1, __shfl_xor_sync(0xffffffffu, mx1, 2));

        const float nm0 = fmaxf(m0r, mx0), nm1 = fmaxf(m1r, mx1);
        const float cor0 = __expf(m0r - nm0), cor1 = __expf(m1r - nm1);
        m0r = nm0; m1r = nm1;
        l0 *= cor0; l1 *= cor1;
#pragma unroll
        for (int nt = 0; nt < 8; nt++) {
            of[nt][0] *= cor0; of[nt][1] *= cor0;
            of[nt][2] *= cor1; of[nt][3] *= cor1;
        }

        // p = exp(s - m), rounded to tf32; same value feeds l and PV.
#pragma unroll
        for (int nt = 0; nt < 16; nt++) {
            float p0 = cvt_tf32(__expf(sf[nt][0] - m0r));
            float p1 = cvt_tf32(__expf(sf[nt][1] - m0r));
            float p2 = cvt_tf32(__expf(sf[nt][2] - m1r));
            float p3 = cvt_tf32(__expf(sf[nt][3] - m1r));
            sf[nt][0] = p0; sf[nt][1] = p1; sf[nt][2] = p2; sf[nt][3] = p3;
            l0 += p0 + p1; l1 += p2 + p3;
        }

        // O += P @ V : relayout P C-frag -> A-frag via quad shuffles
#pragma unroll
        for (int kk = 0; kk < 16; kk++) {
            const float x0 = __shfl_sync(0xffffffffu, sf[kk][0], srcA);
            const float x1 = __shfl_sync(0xffffffffu, sf[kk][1], srcA);
            const float x2 = __shfl_sync(0xffffffffu, sf[kk][2], srcA);
            const float x3 = __shfl_sync(0xffffffffu, sf[kk][3], srcA);
            const float z0 = __shfl_sync(0xffffffffu, sf[kk][0], srcB);
            const float z1 = __shfl_sync(0xffffffffu, sf[kk][1], srcB);
            const float z2 = __shfl_sync(0xffffffffu, sf[kk][2], srcB);
            const float z3 = __shfl_sync(0xffffffffu, sf[kk][3], srcB);
            unsigned a[4];
            a[0] = __float_as_uint((tig & 1) ? x1 : x0);
            a[1] = __float_as_uint((tig & 1) ? x3 : x2);
            a[2] = __float_as_uint((tig & 1) ? z1 : z0);
            a[3] = __float_as_uint((tig & 1) ? z3 : z2);
#pragma unroll
            for (int nt = 0; nt < 8; nt++) {
                unsigned bb[2];
                bb[0] = __float_as_uint(vs[(kk*8 + tig    )*VS_STRIDE + nt*8 + g]);
                bb[1] = __float_as_uint(vs[(kk*8 + tig + 4)*VS_STRIDE + nt*8 + g]);
                mma_tf32(of[nt], a, bb);
            }
        }
    }

    // finalize
    l0 += __shfl_xor_sync(0xffffffffu, l0, 1);
    l0 += __shfl_xor_sync(0xffffffffu, l0, 2);
    l1 += __shfl_xor_sync(0xffffffffu, l1, 1);
    l1 += __shfl_xor_sync(0xffffffffu, l1, 2);
    const float inv0 = 1.f / l0, inv1 = 1.f / l1;

    float* yr0 = y + (size_t)(b*Tc + qt*128 + m0 + g) * Dc + h*DHc;
    float* yr1 = yr0 + (size_t)8 * Dc;
#pragma unroll
    for (int nt = 0; nt < 8; nt++) {
        float2 v0 = make_float2(of[nt][0]*inv0, of[nt][1]*inv0);
        float2 v1 = make_float2(of[nt][2]*inv1, of[nt][3]*inv1);
        *reinterpret_cast<float2*>(yr0 + nt*8 + 2*tig) = v0;
        *reinterpret_cast<float2*>(yr1 + nt*8 + 2*tig) = v1;
    }
}

extern "C" void kernel_launch(void* const* d_in, const int* in_sizes, int n_in,
                              void* d_out, int out_size) {
    const float* x      = (const float*)d_in[0];
    const float* W_qkv  = (const float*)d_in[1];
    const float* W_qlsr = (const float*)d_in[2];
    const float* W_klsr = (const float*)d_in[3];
    const float* core   = (const float*)d_in[4];
    const float* W_o    = (const float*)d_in[5];
    float* out = (float*)d_out;

    float* d_qkv; cudaGetSymbolAddress((void**)&d_qkv, g_qkv);
    float* d_ql;  cudaGetSymbolAddress((void**)&d_ql,  g_ql);
    float* d_kl;  cudaGetSymbolAddress((void**)&d_kl,  g_kl);
    float* d_y;   cudaGetSymbolAddress((void**)&d_y,   g_y);

    // >48KB dynamic smem for attention (idempotent; effective from the first
    // pre-capture correctness call; ignored if it errors during capture)
    cudaFuncSetAttribute(attn_tc_kernel, cudaFuncAttributeMaxDynamicSharedMemorySize, ATTN_SMEM);

    // 1) qkv = x @ W_qkv  (4096 x 3072 x 1024), tf32 tensor cores
    gemm_tf32_kernel<<<dim3(TDc/128, Mrows/128), 256>>>(x, W_qkv, d_qkv, Mrows, TDc, Dc);

    // 2) low-rank projections (core and 1/sqrt(R) folded into ql)
    const float scale = 0.17677669529663687f;  // 1/sqrt(32)
    lsr_kernel<<<Bc*Hc*(Tc/128), 256>>>(0,   W_qlsr, core,   scale, d_ql);
    lsr_kernel<<<Bc*Hc*(Tc/128), 256>>>(Dc,  W_klsr, nullptr, 1.0f, d_kl);

    // 3) causal flash attention (tensor cores) -> g_y
    attn_tc_kernel<<<Bc*Hc*(Tc/128), 256, ATTN_SMEM>>>(d_y);

    // 4) out = y @ W_o  (4096 x 1024 x 1024), tf32 tensor cores
    gemm_tf32_kernel<<<dim3(Dc/128, Mrows/128), 256>>>(d_y, W_o, out, Mrows, Dc, Dc);
}

// round 4
// speedup vs baseline: 2.9430x; 1.2172x over previous
#include <cuda_runtime.h>
#include <cuda_bf16.h>
#include <math.h>

// Problem constants
#define Bc 2
#define Tc 2048
#define Dc 1024
#define Hc 16
#define DHc 64
#define Rc 32
#define TDc (3*Dc)        // 3072
#define Mrows (Bc*Tc)     // 4096
#define LRD 1024          // width of the folded lr buffer (512 ql + 512 kl)

// Scratch (device globals — no allocation allowed)
__device__ float g_wc[(size_t)Dc*LRD];        // folded weights (1024 x 1024)  4 MB
__device__ float g_lr[(size_t)Mrows*LRD];     // [ql | kl] per row            16 MB
__device__ float g_v [(size_t)Mrows*Dc];      // v                            16 MB
__device__ float g_y [(size_t)Mrows*Dc];      // attention output             16 MB

__device__ __forceinline__ float cvt_tf32(float x) {
    float r;
    asm("cvt.rna.tf32.f32 %0, %1;" : "=f"(r) : "f"(x));
    return r;
}

__device__ __forceinline__ void mma_tf32(float* c, const unsigned* a, const unsigned* b) {
    asm volatile(
        "mma.sync.aligned.m16n8k8.row.col.f32.tf32.tf32.f32 "
        "{%0,%1,%2,%3},{%4,%5,%6,%7},{%8,%9},{%0,%1,%2,%3};"
        : "+f"(c[0]), "+f"(c[1]), "+f"(c[2]), "+f"(c[3])
        : "r"(a[0]), "r"(a[1]), "r"(a[2]), "r"(a[3]), "r"(b[0]), "r"(b[1]));
}

// ---------------------------------------------------------------------------
// Weight folding: Wcomb[d, h*32+r]     = sum_dh Wqkv[d, h*64+dh]      * Wql[h,dh,r] * core[h,r]/sqrt(R)
//                 Wcomb[d, 512+h*32+r] = sum_dh Wqkv[d, 1024+h*64+dh] * Wkl[h,dh,r]
// grid (8 d-tiles, 16 h), 256 threads.
// ---------------------------------------------------------------------------
__global__ __launch_bounds__(256) void prep_kernel(const float* __restrict__ Wqkv,
                                                   const float* __restrict__ Wql,
                                                   const float* __restrict__ Wkl,
                                                   const float* __restrict__ core,
                                                   float* __restrict__ wc) {
    const int h  = blockIdx.y;
    const int d0 = blockIdx.x * 128;
    __shared__ float Wq[DHc*Rc], Wk[DHc*Rc];
    __shared__ float Aq[32*DHc], Ak[32*DHc];
    __shared__ float cs[Rc];
    const int tid = threadIdx.x;
    for (int i = tid; i < DHc*Rc; i += 256) {
        Wq[i] = Wql[(size_t)h*DHc*Rc + i];
        Wk[i] = Wkl[(size_t)h*DHc*Rc + i];
    }
    if (tid < Rc) cs[tid] = core[h*Rc + tid] * 0.17677669529663687f;  // 1/sqrt(32)
    __syncthreads();

    for (int c = 0; c < 4; c++) {
        const int dbase = d0 + c*32;
        for (int f = tid; f < 512; f += 256) {
            const int row = f >> 4, cc = (f & 15) << 2;
            float4 va = *reinterpret_cast<const float4*>(&Wqkv[(size_t)(dbase+row)*TDc + h*DHc + cc]);
            *reinterpret_cast<float4*>(&Aq[row*DHc + cc]) = va;
            float4 vb = *reinterpret_cast<const float4*>(&Wqkv[(size_t)(dbase+row)*TDc + Dc + h*DHc + cc]);
            *reinterpret_cast<float4*>(&Ak[row*DHc + cc]) = vb;
        }
        __syncthreads();
        const int r = tid & 31, i0 = tid >> 5;
#pragma unroll
        for (int ii = 0; ii < 4; ii++) {
            const int i = i0*4 + ii;
            float sq = 0.f, sk = 0.f;
#pragma unroll
            for (int dh = 0; dh < DHc; dh++) {
                sq = fmaf(Aq[i*DHc + dh], Wq[dh*Rc + r], sq);
                sk = fmaf(Ak[i*DHc + dh], Wk[dh*Rc + r], sk);
            }
            wc[(size_t)(dbase+i)*LRD + h*Rc + r]       = sq * cs[r];
            wc[(size_t)(dbase+i)*LRD + 512 + h*Rc + r] = sk;
        }
        __syncthreads();
    }
}

// ---------------------------------------------------------------------------
// TF32 tensor-core GEMM: C[M,N] = A[M,K] @ B[K,N'], row-major; B row stride ldb.
// 128x128 block tile, BK=16 double-buffered, 256 threads (8 warps).
// ---------------------------------------------------------------------------
__global__ __launch_bounds__(256) void gemm_tf32_kernel(const float* __restrict__ A,
                                                        const float* __restrict__ B,
                                                        float* __restrict__ C,
                                                        int M, int N, int K, int ldb) {
    __shared__ float As[2][128][20];
    __shared__ float Bs[2][16][136];

    const int tid = threadIdx.x;
    const int warp = tid >> 5, lane = tid & 31;
    const int g = lane >> 2, tig = lane & 3;
    const int wm = warp >> 2;
    const int wn = warp & 3;

    const int fa0 = tid * 2;
    const int aRow0 = fa0 >> 2,       aKc0 = (fa0 & 3) << 2;
    const int aRow1 = (fa0+1) >> 2,   aKc1 = ((fa0+1) & 3) << 2;
    const int bKr0 = fa0 >> 5,        bNc0 = (fa0 & 31) << 2;
    const int bKr1 = (fa0+1) >> 5,    bNc1 = ((fa0+1) & 31) << 2;

    const float* Ab = A + (size_t)blockIdx.y * 128 * K;
    const float* Bb = B + (size_t)blockIdx.x * 128;

    float acc[4][4][4];
#pragma unroll
    for (int i = 0; i < 4; i++)
#pragma unroll
        for (int j = 0; j < 4; j++)
#pragma unroll
            for (int e = 0; e < 4; e++) acc[i][j][e] = 0.f;

    const int nK = K >> 4;

    {
        float4 av0 = *reinterpret_cast<const float4*>(&Ab[(size_t)aRow0 * K + aKc0]);
        float4 av1 = *reinterpret_cast<const float4*>(&Ab[(size_t)aRow1 * K + aKc1]);
        float4 bv0 = *reinterpret_cast<const float4*>(&Bb[(size_t)bKr0 * ldb + bNc0]);
        float4 bv1 = *reinterpret_cast<const float4*>(&Bb[(size_t)bKr1 * ldb + bNc1]);
        As[0][aRow0][aKc0+0] = cvt_tf32(av0.x); As[0][aRow0][aKc0+1] = cvt_tf32(av0.y);
        As[0][aRow0][aKc0+2] = cvt_tf32(av0.z); As[0][aRow0][aKc0+3] = cvt_tf32(av0.w);
        As[0][aRow1][aKc1+0] = cvt_tf32(av1.x); As[0][aRow1][aKc1+1] = cvt_tf32(av1.y);
        As[0][aRow1][aKc1+2] = cvt_tf32(av1.z); As[0][aRow1][aKc1+3] = cvt_tf32(av1.w);
        float4 c0 = make_float4(cvt_tf32(bv0.x), cvt_tf32(bv0.y), cvt_tf32(bv0.z), cvt_tf32(bv0.w));
        float4 c1 = make_float4(cvt_tf32(bv1.x), cvt_tf32(bv1.y), cvt_tf32(bv1.z), cvt_tf32(bv1.w));
        *reinterpret_cast<float4*>(&Bs[0][bKr0][bNc0]) = c0;
        *reinterpret_cast<float4*>(&Bs[0][bKr1][bNc1]) = c1;
    }
    __syncthreads();

    int buf = 0;
    for (int kt = 0; kt < nK; kt++) {
        float4 na0, na1, nb0, nb1;
        const bool more = (kt + 1 < nK);
        if (more) {
            const int k0 = (kt + 1) << 4;
            na0 = *reinterpret_cast<const float4*>(&Ab[(size_t)aRow0 * K + k0 + aKc0]);
            na1 = *reinterpret_cast<const float4*>(&Ab[(size_t)aRow1 * K + k0 + aKc1]);
            nb0 = *reinterpret_cast<const float4*>(&Bb[(size_t)(k0 + bKr0) * ldb + bNc0]);
            nb1 = *reinterpret_cast<const float4*>(&Bb[(size_t)(k0 + bKr1) * ldb + bNc1]);
        }

#pragma unroll
        for (int ks = 0; ks < 16; ks += 8) {
            unsigned afr[4][4], bfr[4][2];
#pragma unroll
            for (int im = 0; im < 4; im++) {
                const int m0 = wm * 64 + im * 16;
                afr[im][0] = __float_as_uint(As[buf][m0 + g     ][ks + tig    ]);
                afr[im][1] = __float_as_uint(As[buf][m0 + g + 8 ][ks + tig    ]);
                afr[im][2] = __float_as_uint(As[buf][m0 + g     ][ks + tig + 4]);
                afr[im][3] = __float_as_uint(As[buf][m0 + g + 8 ][ks + tig + 4]);
            }
#pragma unroll
            for (int in_ = 0; in_ < 4; in_++) {
                const int n0 = wn * 32 + in_ * 8;
                bfr[in_][0] = __float_as_uint(Bs[buf][ks + tig    ][n0 + g]);
                bfr[in_][1] = __float_as_uint(Bs[buf][ks + tig + 4][n0 + g]);
            }
#pragma unroll
            for (int im = 0; im < 4; im++)
#pragma unroll
                for (int in_ = 0; in_ < 4; in_++)
                    mma_tf32(acc[im][in_], afr[im], bfr[in_]);
        }

        if (more) {
            const int nb = buf ^ 1;
            As[nb][aRow0][aKc0+0] = cvt_tf32(na0.x); As[nb][aRow0][aKc0+1] = cvt_tf32(na0.y);
            As[nb][aRow0][aKc0+2] = cvt_tf32(na0.z); As[nb][aRow0][aKc0+3] = cvt_tf32(na0.w);
            As[nb][aRow1][aKc1+0] = cvt_tf32(na1.x); As[nb][aRow1][aKc1+1] = cvt_tf32(na1.y);
            As[nb][aRow1][aKc1+2] = cvt_tf32(na1.z); As[nb][aRow1][aKc1+3] = cvt_tf32(na1.w);
            float4 c0 = make_float4(cvt_tf32(nb0.x), cvt_tf32(nb0.y), cvt_tf32(nb0.z), cvt_tf32(nb0.w));
            float4 c1 = make_float4(cvt_tf32(nb1.x), cvt_tf32(nb1.y), cvt_tf32(nb1.z), cvt_tf32(nb1.w));
            *reinterpret_cast<float4*>(&Bs[nb][bKr0][bNc0]) = c0;
            *reinterpret_cast<float4*>(&Bs[nb][bKr1][bNc1]) = c1;
            __syncthreads();
            buf ^= 1;
        }
    }

#pragma unroll
    for (int im = 0; im < 4; im++) {
        const size_t row0 = (size_t)blockIdx.y * 128 + wm * 64 + im * 16 + g;
#pragma unroll
        for (int in_ = 0; in_ < 4; in_++) {
            const size_t col = (size_t)blockIdx.x * 128 + wn * 32 + in_ * 8 + tig * 2;
            float2 v0 = make_float2(acc[im][in_][0], acc[im][in_][1]);
            float2 v1 = make_float2(acc[im][in_][2], acc[im][in_][3]);
            *reinterpret_cast<float2*>(&C[row0 * N + col])       = v0;
            *reinterpret_cast<float2*>(&C[(row0 + 8) * N + col]) = v1;
        }
    }
}

// ---------------------------------------------------------------------------
// Tensor-core flash attention (tf32 mma).
// Block = (b, h, 128-row q-tile); 256 threads (8 warps), warp = 16 q-rows.
// ql/kl from g_lr (row stride 1024), v from g_v (row stride 1024).
// ---------------------------------------------------------------------------
#define KLS_STRIDE 36
#define VS_STRIDE  72
#define ATTN_SMEM ((128*KLS_STRIDE + 128*VS_STRIDE) * 4)

__global__ __launch_bounds__(256) void attn_tc_kernel(float* __restrict__ y) {
    extern __shared__ float sm[];
    float* kls = sm;                    // [128][36]
    float* vs  = sm + 128*KLS_STRIDE;   // [128][72]

    const int blk = blockIdx.x;
    const int qt = blk & 15;
    const int h  = (blk >> 4) & 15;
    const int b  = blk >> 8;
    const int tid  = threadIdx.x;
    const int warp = tid >> 5, lane = tid & 31;
    const int g = lane >> 2, tig = lane & 3;
    const int m0 = warp * 16;

    // Preload ql A-fragments (scale+core already folded)
    unsigned aq[4][4];
    {
        const float* qlp = g_lr + (size_t)(b*Tc + qt*128 + m0) * LRD + h*Rc;
#pragma unroll
        for (int ks = 0; ks < 4; ks++) {
            aq[ks][0] = __float_as_uint(cvt_tf32(qlp[(size_t)(g    )*LRD + ks*8 + tig    ]));
            aq[ks][1] = __float_as_uint(cvt_tf32(qlp[(size_t)(g + 8)*LRD + ks*8 + tig    ]));
            aq[ks][2] = __float_as_uint(cvt_tf32(qlp[(size_t)(g    )*LRD + ks*8 + tig + 4]));
            aq[ks][3] = __float_as_uint(cvt_tf32(qlp[(size_t)(g + 8)*LRD + ks*8 + tig + 4]));
        }
    }

    float of[8][4];
#pragma unroll
    for (int nt = 0; nt < 8; nt++)
#pragma unroll
        for (int e = 0; e < 4; e++) of[nt][e] = 0.f;
    float m0r = -1e30f, m1r = -1e30f, l0 = 0.f, l1 = 0.f;

    const float* klg = g_lr + (size_t)(b*Tc) * LRD + 512 + h*Rc;
    const float* vg  = g_v  + (size_t)(b*Tc) * Dc + h*DHc;

    const unsigned srcA = (lane & ~3u) | (unsigned)(tig >> 1);
    const unsigned srcB = srcA + 2u;

    for (int kt = 0; kt <= qt; kt++) {
        if (kt) __syncthreads();
#pragma unroll
        for (int i = 0; i < 4; i++) {
            const int f = tid + i*256;
            const int key = f >> 3, r0 = (f & 7) << 2;
            float4 v = *reinterpret_cast<const float4*>(klg + (size_t)(kt*128 + key)*LRD + r0);
            float* dst = kls + key*KLS_STRIDE + r0;
            dst[0] = cvt_tf32(v.x); dst[1] = cvt_tf32(v.y);
            dst[2] = cvt_tf32(v.z); dst[3] = cvt_tf32(v.w);
        }
#pragma unroll
        for (int i = 0; i < 8; i++) {
            const int f = tid + i*256;
            const int key = f >> 4, j = (f & 15) << 2;
            float4 v = *reinterpret_cast<const float4*>(vg + (size_t)(kt*128 + key)*Dc + j);
            float* dst = vs + key*VS_STRIDE + j;
            dst[0] = cvt_tf32(v.x); dst[1] = cvt_tf32(v.y);
            dst[2] = cvt_tf32(v.z); dst[3] = cvt_tf32(v.w);
        }
        __syncthreads();

        // S = ql @ kl^T  (16 x 128)
        float sf[16][4];
#pragma unroll
        for (int nt = 0; nt < 16; nt++) {
#pragma unroll
            for (int e = 0; e < 4; e++) sf[nt][e] = 0.f;
#pragma unroll
            for (int ks = 0; ks < 4; ks++) {
                unsigned bb[2];
                bb[0] = __float_as_uint(kls[(nt*8 + g)*KLS_STRIDE + ks*8 + tig    ]);
                bb[1] = __float_as_uint(kls[(nt*8 + g)*KLS_STRIDE + ks*8 + tig + 4]);
                mma_tf32(sf[nt], aq[ks], bb);
            }
        }

        // causal mask on diagonal tile
        if (kt == qt) {
            const int r0l = m0 + g, r1l = r0l + 8;
#pragma unroll
            for (int nt = 0; nt < 16; nt++) {
                const int c = nt*8 + 2*tig;
                if (c     > r0l) sf[nt][0] = -1e30f;
                if (c + 1 > r0l) sf[nt][1] = -1e30f;
                if (c     > r1l) sf[nt][2] = -1e30f;
                if (c + 1 > r1l) sf[nt][3] = -1e30f;
            }
        }

        // row max
        float mx0 = -1e30f, mx1 = -1e30f;
#pragma unroll
        for (int nt = 0; nt < 16; nt++) {
            mx0 = fmaxf(mx0, fmaxf(sf[nt][0], sf[nt][1]));
            mx1 = fmaxf(mx1, fmaxf(sf[nt][2], sf[nt][3]));
        }
        mx0 = fmaxf(mx0, __shfl_xor_sync(0xffffffffu, mx0, 1));
        mx0 = fmaxf(mx0, __shfl_xor_sync(0xffffffffu, mx0, 2));
        mx1 = fmaxf(mx1, __shfl_xor_sync(0xffffffffu, mx1, 1));
        mx1 = fmaxf(mx1, __shfl_xor_sync(0xffffffffu, mx1, 2));

        const float nm0 = fmaxf(m0r, mx0), nm1 = fmaxf(m1r, mx1);
        const float cor0 = __expf(m0r - nm0), cor1 = __expf(m1r - nm1);
        m0r = nm0; m1r = nm1;
        l0 *= cor0; l1 *= cor1;
#pragma unroll
        for (int nt = 0; nt < 8; nt++) {
            of[nt][0] *= cor0; of[nt][1] *= cor0;
            of[nt][2] *= cor1; of[nt][3] *= cor1;
        }

        // p = exp(s - m) rounded to tf32; same value feeds l and PV
#pragma unroll
        for (int nt = 0; nt < 16; nt++) {
            float p0 = cvt_tf32(__expf(sf[nt][0] - m0r));
            float p1 = cvt_tf32(__expf(sf[nt][1] - m0r));
            float p2 = cvt_tf32(__expf(sf[nt][2] - m1r));
            float p3 = cvt_tf32(__expf(sf[nt][3] - m1r));
            sf[nt][0] = p0; sf[nt][1] = p1; sf[nt][2] = p2; sf[nt][3] = p3;
            l0 += p0 + p1; l1 += p2 + p3;
        }

        // O += P @ V (C-frag -> A-frag relayout via quad shuffles)
#pragma unroll
        for (int kk = 0; kk < 16; kk++) {
            const float x0 = __shfl_sync(0xffffffffu, sf[kk][0], srcA);
            const float x1 = __shfl_sync(0xffffffffu, sf[kk][1], srcA);
            const float x2 = __shfl_sync(0xffffffffu, sf[kk][2], srcA);
            const float x3 = __shfl_sync(0xffffffffu, sf[kk][3], srcA);
            const float z0 = __shfl_sync(0xffffffffu, sf[kk][0], srcB);
            const float z1 = __shfl_sync(0xffffffffu, sf[kk][1], srcB);
            const float z2 = __shfl_sync(0xffffffffu, sf[kk][2], srcB);
            const float z3 = __shfl_sync(0xffffffffu, sf[kk][3], srcB);
            unsigned a[4];
            a[0] = __float_as_uint((tig & 1) ? x1 : x0);
            a[1] = __float_as_uint((tig & 1) ? x3 : x2);
            a[2] = __float_as_uint((tig & 1) ? z1 : z0);
            a[3] = __float_as_uint((tig & 1) ? z3 : z2);
#pragma unroll
            for (int nt = 0; nt < 8; nt++) {
                unsigned bb[2];
                bb[0] = __float_as_uint(vs[(kk*8 + tig    )*VS_STRIDE + nt*8 + g]);
                bb[1] = __float_as_uint(vs[(kk*8 + tig + 4)*VS_STRIDE + nt*8 + g]);
                mma_tf32(of[nt], a, bb);
            }
        }
    }

    // finalize
    l0 += __shfl_xor_sync(0xffffffffu, l0, 1);
    l0 += __shfl_xor_sync(0xffffffffu, l0, 2);
    l1 += __shfl_xor_sync(0xffffffffu, l1, 1);
    l1 += __shfl_xor_sync(0xffffffffu, l1, 2);
    const float inv0 = 1.f / l0, inv1 = 1.f / l1;

    float* yr0 = y + (size_t)(b*Tc + qt*128 + m0 + g) * Dc + h*DHc;
    float* yr1 = yr0 + (size_t)8 * Dc;
#pragma unroll
    for (int nt = 0; nt < 8; nt++) {
        float2 v0 = make_float2(of[nt][0]*inv0, of[nt][1]*inv0);
        float2 v1 = make_float2(of[nt][2]*inv1, of[nt][3]*inv1);
        *reinterpret_cast<float2*>(yr0 + nt*8 + 2*tig) = v0;
        *reinterpret_cast<float2*>(yr1 + nt*8 + 2*tig) = v1;
    }
}

extern "C" void kernel_launch(void* const* d_in, const int* in_sizes, int n_in,
                              void* d_out, int out_size) {
    const float* x      = (const float*)d_in[0];
    const float* W_qkv  = (const float*)d_in[1];
    const float* W_qlsr = (const float*)d_in[2];
    const float* W_klsr = (const float*)d_in[3];
    const float* core   = (const float*)d_in[4];
    const float* W_o    = (const float*)d_in[5];
    float* out = (float*)d_out;

    float* d_wc; cudaGetSymbolAddress((void**)&d_wc, g_wc);
    float* d_lr; cudaGetSymbolAddress((void**)&d_lr, g_lr);
    float* d_v;  cudaGetSymbolAddress((void**)&d_v,  g_v);
    float* d_y;  cudaGetSymbolAddress((void**)&d_y,  g_y);

    cudaFuncSetAttribute(attn_tc_kernel, cudaFuncAttributeMaxDynamicSharedMemorySize, ATTN_SMEM);

    // 0) fold LSR weights (+core+scale) into a 1024x1024 combined projection
    prep_kernel<<<dim3(8, 16), 256>>>(W_qkv, W_qlsr, W_klsr, core, d_wc);

    // 1a) [ql|kl] = x @ Wcomb   (4096 x 1024 x 1024)
    gemm_tf32_kernel<<<dim3(LRD/128, Mrows/128), 256>>>(x, d_wc, d_lr, Mrows, LRD, Dc, LRD);
    // 1b) v = x @ W_qkv[:, 2D:3D]  (4096 x 1024 x 1024, ldb=3072)
    gemm_tf32_kernel<<<dim3(Dc/128, Mrows/128), 256>>>(x, W_qkv + 2*Dc, d_v, Mrows, Dc, Dc, TDc);

    // 2) causal flash attention (tensor cores) -> g_y
    attn_tc_kernel<<<Bc*Hc*(Tc/128), 256, ATTN_SMEM>>>(d_y);

    // 3) out = y @ W_o  (4096 x 1024 x 1024)
    gemm_tf32_kernel<<<dim3(Dc/128, Mrows/128), 256>>>(d_y, W_o, out, Mrows, Dc, Dc, Dc);
}

// round 5
// speedup vs baseline: 3.0942x; 1.0514x over previous
#include <cuda_runtime.h>
#include <cuda_bf16.h>
#include <math.h>

// Problem constants
#define Bc 2
#define Tc 2048
#define Dc 1024
#define Hc 16
#define DHc 64
#define Rc 32
#define TDc (3*Dc)        // 3072
#define Mrows (Bc*Tc)     // 4096
#define LRD 1024          // width of the folded lr buffer (512 ql + 512 kl)

// Scratch (device globals — no allocation allowed)
__device__ float g_wc[(size_t)Dc*LRD];        // folded weights (1024 x 1024)
__device__ float g_lr[(size_t)Mrows*LRD];     // [ql | kl] per row
__device__ float g_v [(size_t)Mrows*Dc];      // v
__device__ float g_y [(size_t)Mrows*Dc];      // attention output

__device__ __forceinline__ float cvt_tf32(float x) {
    float r;
    asm("cvt.rna.tf32.f32 %0, %1;" : "=f"(r) : "f"(x));
    return r;
}

__device__ __forceinline__ void mma_tf32(float* c, const unsigned* a, const unsigned* b) {
    asm volatile(
        "mma.sync.aligned.m16n8k8.row.col.f32.tf32.tf32.f32 "
        "{%0,%1,%2,%3},{%4,%5,%6,%7},{%8,%9},{%0,%1,%2,%3};"
        : "+f"(c[0]), "+f"(c[1]), "+f"(c[2]), "+f"(c[3])
        : "r"(a[0]), "r"(a[1]), "r"(a[2]), "r"(a[3]), "r"(b[0]), "r"(b[1]));
}

// ---------------------------------------------------------------------------
// Weight folding (unchanged)
// ---------------------------------------------------------------------------
__global__ __launch_bounds__(256) void prep_kernel(const float* __restrict__ Wqkv,
                                                   const float* __restrict__ Wql,
                                                   const float* __restrict__ Wkl,
                                                   const float* __restrict__ core,
                                                   float* __restrict__ wc) {
    const int h  = blockIdx.y;
    const int d0 = blockIdx.x * 128;
    __shared__ float Wq[DHc*Rc], Wk[DHc*Rc];
    __shared__ float Aq[32*DHc], Ak[32*DHc];
    __shared__ float cs[Rc];
    const int tid = threadIdx.x;
    for (int i = tid; i < DHc*Rc; i += 256) {
        Wq[i] = Wql[(size_t)h*DHc*Rc + i];
        Wk[i] = Wkl[(size_t)h*DHc*Rc + i];
    }
    if (tid < Rc) cs[tid] = core[h*Rc + tid] * 0.17677669529663687f;
    __syncthreads();

    for (int c = 0; c < 4; c++) {
        const int dbase = d0 + c*32;
        for (int f = tid; f < 512; f += 256) {
            const int row = f >> 4, cc = (f & 15) << 2;
            float4 va = *reinterpret_cast<const float4*>(&Wqkv[(size_t)(dbase+row)*TDc + h*DHc + cc]);
            *reinterpret_cast<float4*>(&Aq[row*DHc + cc]) = va;
            float4 vb = *reinterpret_cast<const float4*>(&Wqkv[(size_t)(dbase+row)*TDc + Dc + h*DHc + cc]);
            *reinterpret_cast<float4*>(&Ak[row*DHc + cc]) = vb;
        }
        __syncthreads();
        const int r = tid & 31, i0 = tid >> 5;
#pragma unroll
        for (int ii = 0; ii < 4; ii++) {
            const int i = i0*4 + ii;
            float sq = 0.f, sk = 0.f;
#pragma unroll
            for (int dh = 0; dh < DHc; dh++) {
                sq = fmaf(Aq[i*DHc + dh], Wq[dh*Rc + r], sq);
                sk = fmaf(Ak[i*DHc + dh], Wk[dh*Rc + r], sk);
            }
            wc[(size_t)(dbase+i)*LRD + h*Rc + r]       = sq * cs[r];
            wc[(size_t)(dbase+i)*LRD + 512 + h*Rc + r] = sk;
        }
        __syncthreads();
    }
}

// ---------------------------------------------------------------------------
// TF32 tensor-core GEMM (unchanged)
// ---------------------------------------------------------------------------
__global__ __launch_bounds__(256) void gemm_tf32_kernel(const float* __restrict__ A,
                                                        const float* __restrict__ B,
                                                        float* __restrict__ C,
                                                        int M, int N, int K, int ldb) {
    __shared__ float As[2][128][20];
    __shared__ float Bs[2][16][136];

    const int tid = threadIdx.x;
    const int warp = tid >> 5, lane = tid & 31;
    const int g = lane >> 2, tig = lane & 3;
    const int wm = warp >> 2;
    const int wn = warp & 3;

    const int fa0 = tid * 2;
    const int aRow0 = fa0 >> 2,       aKc0 = (fa0 & 3) << 2;
    const int aRow1 = (fa0+1) >> 2,   aKc1 = ((fa0+1) & 3) << 2;
    const int bKr0 = fa0 >> 5,        bNc0 = (fa0 & 31) << 2;
    const int bKr1 = (fa0+1) >> 5,    bNc1 = ((fa0+1) & 31) << 2;

    const float* Ab = A + (size_t)blockIdx.y * 128 * K;
    const float* Bb = B + (size_t)blockIdx.x * 128;

    float acc[4][4][4];
#pragma unroll
    for (int i = 0; i < 4; i++)
#pragma unroll
        for (int j = 0; j < 4; j++)
#pragma unroll
            for (int e = 0; e < 4; e++) acc[i][j][e] = 0.f;

    const int nK = K >> 4;

    {
        float4 av0 = *reinterpret_cast<const float4*>(&Ab[(size_t)aRow0 * K + aKc0]);
        float4 av1 = *reinterpret_cast<const float4*>(&Ab[(size_t)aRow1 * K + aKc1]);
        float4 bv0 = *reinterpret_cast<const float4*>(&Bb[(size_t)bKr0 * ldb + bNc0]);
        float4 bv1 = *reinterpret_cast<const float4*>(&Bb[(size_t)bKr1 * ldb + bNc1]);
        As[0][aRow0][aKc0+0] = cvt_tf32(av0.x); As[0][aRow0][aKc0+1] = cvt_tf32(av0.y);
        As[0][aRow0][aKc0+2] = cvt_tf32(av0.z); As[0][aRow0][aKc0+3] = cvt_tf32(av0.w);
        As[0][aRow1][aKc1+0] = cvt_tf32(av1.x); As[0][aRow1][aKc1+1] = cvt_tf32(av1.y);
        As[0][aRow1][aKc1+2] = cvt_tf32(av1.z); As[0][aRow1][aKc1+3] = cvt_tf32(av1.w);
        float4 c0 = make_float4(cvt_tf32(bv0.x), cvt_tf32(bv0.y), cvt_tf32(bv0.z), cvt_tf32(bv0.w));
        float4 c1 = make_float4(cvt_tf32(bv1.x), cvt_tf32(bv1.y), cvt_tf32(bv1.z), cvt_tf32(bv1.w));
        *reinterpret_cast<float4*>(&Bs[0][bKr0][bNc0]) = c0;
        *reinterpret_cast<float4*>(&Bs[0][bKr1][bNc1]) = c1;
    }
    __syncthreads();

    int buf = 0;
    for (int kt = 0; kt < nK; kt++) {
        float4 na0, na1, nb0, nb1;
        const bool more = (kt + 1 < nK);
        if (more) {
            const int k0 = (kt + 1) << 4;
            na0 = *reinterpret_cast<const float4*>(&Ab[(size_t)aRow0 * K + k0 + aKc0]);
            na1 = *reinterpret_cast<const float4*>(&Ab[(size_t)aRow1 * K + k0 + aKc1]);
            nb0 = *reinterpret_cast<const float4*>(&Bb[(size_t)(k0 + bKr0) * ldb + bNc0]);
            nb1 = *reinterpret_cast<const float4*>(&Bb[(size_t)(k0 + bKr1) * ldb + bNc1]);
        }

#pragma unroll
        for (int ks = 0; ks < 16; ks += 8) {
            unsigned afr[4][4], bfr[4][2];
#pragma unroll
            for (int im = 0; im < 4; im++) {
                const int m0 = wm * 64 + im * 16;
                afr[im][0] = __float_as_uint(As[buf][m0 + g     ][ks + tig    ]);
                afr[im][1] = __float_as_uint(As[buf][m0 + g + 8 ][ks + tig    ]);
                afr[im][2] = __float_as_uint(As[buf][m0 + g     ][ks + tig + 4]);
                afr[im][3] = __float_as_uint(As[buf][m0 + g + 8 ][ks + tig + 4]);
            }
#pragma unroll
            for (int in_ = 0; in_ < 4; in_++) {
                const int n0 = wn * 32 + in_ * 8;
                bfr[in_][0] = __float_as_uint(Bs[buf][ks + tig    ][n0 + g]);
                bfr[in_][1] = __float_as_uint(Bs[buf][ks + tig + 4][n0 + g]);
            }
#pragma unroll
            for (int im = 0; im < 4; im++)
#pragma unroll
                for (int in_ = 0; in_ < 4; in_++)
                    mma_tf32(acc[im][in_], afr[im], bfr[in_]);
        }

        if (more) {
            const int nb = buf ^ 1;
            As[nb][aRow0][aKc0+0] = cvt_tf32(na0.x); As[nb][aRow0][aKc0+1] = cvt_tf32(na0.y);
            As[nb][aRow0][aKc0+2] = cvt_tf32(na0.z); As[nb][aRow0][aKc0+3] = cvt_tf32(na0.w);
            As[nb][aRow1][aKc1+0] = cvt_tf32(na1.x); As[nb][aRow1][aKc1+1] = cvt_tf32(na1.y);
            As[nb][aRow1][aKc1+2] = cvt_tf32(na1.z); As[nb][aRow1][aKc1+3] = cvt_tf32(na1.w);
            float4 c0 = make_float4(cvt_tf32(nb0.x), cvt_tf32(nb0.y), cvt_tf32(nb0.z), cvt_tf32(nb0.w));
            float4 c1 = make_float4(cvt_tf32(nb1.x), cvt_tf32(nb1.y), cvt_tf32(nb1.z), cvt_tf32(nb1.w));
            *reinterpret_cast<float4*>(&Bs[nb][bKr0][bNc0]) = c0;
            *reinterpret_cast<float4*>(&Bs[nb][bKr1][bNc1]) = c1;
            __syncthreads();
            buf ^= 1;
        }
    }

#pragma unroll
    for (int im = 0; im < 4; im++) {
        const size_t row0 = (size_t)blockIdx.y * 128 + wm * 64 + im * 16 + g;
#pragma unroll
        for (int in_ = 0; in_ < 4; in_++) {
            const size_t col = (size_t)blockIdx.x * 128 + wn * 32 + in_ * 8 + tig * 2;
            float2 v0 = make_float2(acc[im][in_][0], acc[im][in_][1]);
            float2 v1 = make_float2(acc[im][in_][2], acc[im][in_][3]);
            *reinterpret_cast<float2*>(&C[row0 * N + col])       = v0;
            *reinterpret_cast<float2*>(&C[(row0 + 8) * N + col]) = v1;
        }
    }
}

// ---------------------------------------------------------------------------
// Tensor-core flash attention, 64-key tiles, 2 CTAs/SM, heavy-first schedule.
// Block = (b, h, 128-row q-tile); 256 threads (8 warps), warp = 16 q-rows.
// ---------------------------------------------------------------------------
#define KLS_STRIDE 36
#define VS_STRIDE  72
#define KT 64

__global__ __launch_bounds__(256, 2) void attn_tc_kernel(float* __restrict__ y) {
    __shared__ float kls[KT*KLS_STRIDE];   // 9.2 KB
    __shared__ float vs [KT*VS_STRIDE];    // 18.4 KB

    const int blk = blockIdx.x;
    const int qt = 15 - (blk & 15);        // heavy tiles first
    const int h  = (blk >> 4) & 15;
    const int b  = blk >> 8;
    const int tid  = threadIdx.x;
    const int warp = tid >> 5, lane = tid & 31;
    const int g = lane >> 2, tig = lane & 3;
    const int m0 = warp * 16;

    // Preload ql A-fragments (scale+core already folded)
    unsigned aq[4][4];
    {
        const float* qlp = g_lr + (size_t)(b*Tc + qt*128 + m0) * LRD + h*Rc;
#pragma unroll
        for (int ks = 0; ks < 4; ks++) {
            aq[ks][0] = __float_as_uint(cvt_tf32(qlp[(size_t)(g    )*LRD + ks*8 + tig    ]));
            aq[ks][1] = __float_as_uint(cvt_tf32(qlp[(size_t)(g + 8)*LRD + ks*8 + tig    ]));
            aq[ks][2] = __float_as_uint(cvt_tf32(qlp[(size_t)(g    )*LRD + ks*8 + tig + 4]));
            aq[ks][3] = __float_as_uint(cvt_tf32(qlp[(size_t)(g + 8)*LRD + ks*8 + tig + 4]));
        }
    }

    float of[8][4];
#pragma unroll
    for (int nt = 0; nt < 8; nt++)
#pragma unroll
        for (int e = 0; e < 4; e++) of[nt][e] = 0.f;
    float m0r = -1e30f, m1r = -1e30f, l0 = 0.f, l1 = 0.f;

    const float* klg = g_lr + (size_t)(b*Tc) * LRD + 512 + h*Rc;
    const float* vg  = g_v  + (size_t)(b*Tc) * Dc + h*DHc;

    const unsigned srcA = (lane & ~3u) | (unsigned)(tig >> 1);
    const unsigned srcB = srcA + 2u;

    const int ktMax = 2*qt + 1;            // inclusive, 64-key tiles
    for (int kt = 0; kt <= ktMax; kt++) {
        if (kt) __syncthreads();
        // cooperative loads (tf32 rounding)
#pragma unroll
        for (int i = 0; i < 2; i++) {
            const int f = tid + i*256;     // 512 float4 for kl
            const int key = f >> 3, r0 = (f & 7) << 2;
            float4 v = *reinterpret_cast<const float4*>(klg + (size_t)(kt*KT + key)*LRD + r0);
            float* dst = kls + key*KLS_STRIDE + r0;
            dst[0] = cvt_tf32(v.x); dst[1] = cvt_tf32(v.y);
            dst[2] = cvt_tf32(v.z); dst[3] = cvt_tf32(v.w);
        }
#pragma unroll
        for (int i = 0; i < 4; i++) {
            const int f = tid + i*256;     // 1024 float4 for v
            const int key = f >> 4, j = (f & 15) << 2;
            float4 v = *reinterpret_cast<const float4*>(vg + (size_t)(kt*KT + key)*Dc + j);
            float* dst = vs + key*VS_STRIDE + j;
            dst[0] = cvt_tf32(v.x); dst[1] = cvt_tf32(v.y);
            dst[2] = cvt_tf32(v.z); dst[3] = cvt_tf32(v.w);
        }
        __syncthreads();

        const bool masked = (kt >= 2*qt);
        const int cbase = (kt - 2*qt) * KT;     // local column base for mask
        if (masked && (m0 + 15) < cbase) continue;  // warp fully masked

        // S = ql @ kl^T  (16 x 64)
        float sf[8][4];
#pragma unroll
        for (int nt = 0; nt < 8; nt++) {
#pragma unroll
            for (int e = 0; e < 4; e++) sf[nt][e] = 0.f;
#pragma unroll
            for (int ks = 0; ks < 4; ks++) {
                unsigned bb[2];
                bb[0] = __float_as_uint(kls[(nt*8 + g)*KLS_STRIDE + ks*8 + tig    ]);
                bb[1] = __float_as_uint(kls[(nt*8 + g)*KLS_STRIDE + ks*8 + tig + 4]);
                mma_tf32(sf[nt], aq[ks], bb);
            }
        }

        if (masked) {
            const int r0l = m0 + g, r1l = r0l + 8;
#pragma unroll
            for (int nt = 0; nt < 8; nt++) {
                const int c = cbase + nt*8 + 2*tig;
                if (c     > r0l) sf[nt][0] = -1e30f;
                if (c + 1 > r0l) sf[nt][1] = -1e30f;
                if (c     > r1l) sf[nt][2] = -1e30f;
                if (c + 1 > r1l) sf[nt][3] = -1e30f;
            }
        }

        // row max
        float mx0 = -1e30f, mx1 = -1e30f;
#pragma unroll
        for (int nt = 0; nt < 8; nt++) {
            mx0 = fmaxf(mx0, fmaxf(sf[nt][0], sf[nt][1]));
            mx1 = fmaxf(mx1, fmaxf(sf[nt][2], sf[nt][3]));
        }
        mx0 = fmaxf(mx0, __shfl_xor_sync(0xffffffffu, mx0, 1));
        mx0 = fmaxf(mx0, __shfl_xor_sync(0xffffffffu, mx0, 2));
        mx1 = fmaxf(mx1, __shfl_xor_sync(0xffffffffu, mx1, 1));
        mx1 = fmaxf(mx1, __shfl_xor_sync(0xffffffffu, mx1, 2));

        const float nm0 = fmaxf(m0r, mx0), nm1 = fmaxf(m1r, mx1);
        const float cor0 = __expf(m0r - nm0), cor1 = __expf(m1r - nm1);
        m0r = nm0; m1r = nm1;
        l0 *= cor0; l1 *= cor1;
#pragma unroll
        for (int nt = 0; nt < 8; nt++) {
            of[nt][0] *= cor0; of[nt][1] *= cor0;
            of[nt][2] *= cor1; of[nt][3] *= cor1;
        }

        // p = exp(s - m) rounded to tf32; same value feeds l and PV
#pragma unroll
        for (int nt = 0; nt < 8; nt++) {
            float p0 = cvt_tf32(__expf(sf[nt][0] - m0r));
            float p1 = cvt_tf32(__expf(sf[nt][1] - m0r));
            float p2 = cvt_tf32(__expf(sf[nt][2] - m1r));
            float p3 = cvt_tf32(__expf(sf[nt][3] - m1r));
            sf[nt][0] = p0; sf[nt][1] = p1; sf[nt][2] = p2; sf[nt][3] = p3;
            l0 += p0 + p1; l1 += p2 + p3;
        }

        // O += P @ V (C-frag -> A-frag relayout via quad shuffles)
#pragma unroll
        for (int kk = 0; kk < 8; kk++) {
            const float x0 = __shfl_sync(0xffffffffu, sf[kk][0], srcA);
            const float x1 = __shfl_sync(0xffffffffu, sf[kk][1], srcA);
            const float x2 = __shfl_sync(0xffffffffu, sf[kk][2], srcA);
            const float x3 = __shfl_sync(0xffffffffu, sf[kk][3], srcA);
            const float z0 = __shfl_sync(0xffffffffu, sf[kk][0], srcB);
            const float z1 = __shfl_sync(0xffffffffu, sf[kk][1], srcB);
            const float z2 = __shfl_sync(0xffffffffu, sf[kk][2], srcB);
            const float z3 = __shfl_sync(0xffffffffu, sf[kk][3], srcB);
            unsigned a[4];
            a[0] = __float_as_uint((tig & 1) ? x1 : x0);
            a[1] = __float_as_uint((tig & 1) ? x3 : x2);
            a[2] = __float_as_uint((tig & 1) ? z1 : z0);
            a[3] = __float_as_uint((tig & 1) ? z3 : z2);
#pragma unroll
            for (int nt = 0; nt < 8; nt++) {
                unsigned bb[2];
                bb[0] = __float_as_uint(vs[(kk*8 + tig    )*VS_STRIDE + nt*8 + g]);
                bb[1] = __float_as_uint(vs[(kk*8 + tig + 4)*VS_STRIDE + nt*8 + g]);
                mma_tf32(of[nt], a, bb);
            }
        }
    }

    // finalize
    l0 += __shfl_xor_sync(0xffffffffu, l0, 1);
    l0 += __shfl_xor_sync(0xffffffffu, l0, 2);
    l1 += __shfl_xor_sync(0xffffffffu, l1, 1);
    l1 += __shfl_xor_sync(0xffffffffu, l1, 2);
    const float inv0 = 1.f / l0, inv1 = 1.f / l1;

    float* yr0 = y + (size_t)(b*Tc + qt*128 + m0 + g) * Dc + h*DHc;
    float* yr1 = yr0 + (size_t)8 * Dc;
#pragma unroll
    for (int nt = 0; nt < 8; nt++) {
        float2 v0 = make_float2(of[nt][0]*inv0, of[nt][1]*inv0);
        float2 v1 = make_float2(of[nt][2]*inv1, of[nt][3]*inv1);
        *reinterpret_cast<float2*>(yr0 + nt*8 + 2*tig) = v0;
        *reinterpret_cast<float2*>(yr1 + nt*8 + 2*tig) = v1;
    }
}

extern "C" void kernel_launch(void* const* d_in, const int* in_sizes, int n_in,
                              void* d_out, int out_size) {
    const float* x      = (const float*)d_in[0];
    const float* W_qkv  = (const float*)d_in[1];
    const float* W_qlsr = (const float*)d_in[2];
    const float* W_klsr = (const float*)d_in[3];
    const float* core   = (const float*)d_in[4];
    const float* W_o    = (const float*)d_in[5];
    float* out = (float*)d_out;

    float* d_wc; cudaGetSymbolAddress((void**)&d_wc, g_wc);
    float* d_lr; cudaGetSymbolAddress((void**)&d_lr, g_lr);
    float* d_v;  cudaGetSymbolAddress((void**)&d_v,  g_v);
    float* d_y;  cudaGetSymbolAddress((void**)&d_y,  g_y);

    // 0) fold LSR weights (+core+scale) into a 1024x1024 combined projection
    prep_kernel<<<dim3(8, 16), 256>>>(W_qkv, W_qlsr, W_klsr, core, d_wc);

    // 1a) [ql|kl] = x @ Wcomb   (4096 x 1024 x 1024)
    gemm_tf32_kernel<<<dim3(LRD/128, Mrows/128), 256>>>(x, d_wc, d_lr, Mrows, LRD, Dc, LRD);
    // 1b) v = x @ W_qkv[:, 2D:3D]  (4096 x 1024 x 1024, ldb=3072)
    gemm_tf32_kernel<<<dim3(Dc/128, Mrows/128), 256>>>(x, W_qkv + 2*Dc, d_v, Mrows, Dc, Dc, TDc);

    // 2) causal flash attention (tensor cores, 64-key tiles) -> g_y
    attn_tc_kernel<<<Bc*Hc*(Tc/128), 256>>>(d_y);

    // 3) out = y @ W_o  (4096 x 1024 x 1024)
    gemm_tf32_kernel<<<dim3(Dc/128, Mrows/128), 256>>>(d_y, W_o, out, Mrows, Dc, Dc, Dc);
}

// round 6
// speedup vs baseline: 3.4172x; 1.1044x over previous
#include <cuda_runtime.h>
#include <cuda_bf16.h>
#include <math.h>

// Problem constants
#define Bc 2
#define Tc 2048
#define Dc 1024
#define Hc 16
#define DHc 64
#define Rc 32
#define TDc (3*Dc)        // 3072
#define Mrows (Bc*Tc)     // 4096
#define LRW 2048          // combined row: [ql(512) | kl(512) | v(1024)]

// Scratch (device globals — no allocation allowed)
__device__ float g_wc[(size_t)Dc*LRW];        // folded weights (1024 x 2048)  8 MB
__device__ float g_lr[(size_t)Mrows*LRW];     // [ql | kl | v] per row        32 MB
__device__ float g_y [(size_t)Mrows*Dc];      // attention output             16 MB

__device__ __forceinline__ float cvt_tf32(float x) {
    float r;
    asm("cvt.rna.tf32.f32 %0, %1;" : "=f"(r) : "f"(x));
    return r;
}

__device__ __forceinline__ void mma_tf32(float* c, const unsigned* a, const unsigned* b) {
    asm volatile(
        "mma.sync.aligned.m16n8k8.row.col.f32.tf32.tf32.f32 "
        "{%0,%1,%2,%3},{%4,%5,%6,%7},{%8,%9},{%0,%1,%2,%3};"
        : "+f"(c[0]), "+f"(c[1]), "+f"(c[2]), "+f"(c[3])
        : "r"(a[0]), "r"(a[1]), "r"(a[2]), "r"(a[3]), "r"(b[0]), "r"(b[1]));
}

__device__ __forceinline__ void cp16(void* smem, const void* gmem) {
    unsigned saddr = (unsigned)__cvta_generic_to_shared(smem);
    asm volatile("cp.async.ca.shared.global [%0], [%1], 16;" :: "r"(saddr), "l"(gmem));
}
__device__ __forceinline__ void cp_commit() {
    asm volatile("cp.async.commit_group;");
}
template<int N>
__device__ __forceinline__ void cp_wait() {
    asm volatile("cp.async.wait_group %0;" :: "n"(N));
}

// ---------------------------------------------------------------------------
// Weight folding: wc[d, h*32+r] = sum Wqkv[d,h*64+dh]*Wql[h,dh,r]*core*scale
//                 wc[d, 512+h*32+r] = sum Wqkv[d,1024+h*64+dh]*Wkl[h,dh,r]
// ---------------------------------------------------------------------------
__global__ __launch_bounds__(256) void prep_kernel(const float* __restrict__ Wqkv,
                                                   const float* __restrict__ Wql,
                                                   const float* __restrict__ Wkl,
                                                   const float* __restrict__ core,
                                                   float* __restrict__ wc) {
    const int h  = blockIdx.y;
    const int d0 = blockIdx.x * 128;
    __shared__ float Wq[DHc*Rc], Wk[DHc*Rc];
    __shared__ float Aq[32*DHc], Ak[32*DHc];
    __shared__ float cs[Rc];
    const int tid = threadIdx.x;
    for (int i = tid; i < DHc*Rc; i += 256) {
        Wq[i] = Wql[(size_t)h*DHc*Rc + i];
        Wk[i] = Wkl[(size_t)h*DHc*Rc + i];
    }
    if (tid < Rc) cs[tid] = core[h*Rc + tid] * 0.17677669529663687f;
    __syncthreads();

    for (int c = 0; c < 4; c++) {
        const int dbase = d0 + c*32;
        for (int f = tid; f < 512; f += 256) {
            const int row = f >> 4, cc = (f & 15) << 2;
            float4 va = *reinterpret_cast<const float4*>(&Wqkv[(size_t)(dbase+row)*TDc + h*DHc + cc]);
            *reinterpret_cast<float4*>(&Aq[row*DHc + cc]) = va;
            float4 vb = *reinterpret_cast<const float4*>(&Wqkv[(size_t)(dbase+row)*TDc + Dc + h*DHc + cc]);
            *reinterpret_cast<float4*>(&Ak[row*DHc + cc]) = vb;
        }
        __syncthreads();
        const int r = tid & 31, i0 = tid >> 5;
#pragma unroll
        for (int ii = 0; ii < 4; ii++) {
            const int i = i0*4 + ii;
            float sq = 0.f, sk = 0.f;
#pragma unroll
            for (int dh = 0; dh < DHc; dh++) {
                sq = fmaf(Aq[i*DHc + dh], Wq[dh*Rc + r], sq);
                sk = fmaf(Ak[i*DHc + dh], Wk[dh*Rc + r], sk);
            }
            wc[(size_t)(dbase+i)*LRW + h*Rc + r]       = sq * cs[r];
            wc[(size_t)(dbase+i)*LRW + 512 + h*Rc + r] = sk;
        }
        __syncthreads();
    }
}

// Copy V weight block: wc[:, 1024+j] = Wqkv[:, 2048+j]
__global__ __launch_bounds__(256) void copyv_kernel(const float* __restrict__ Wqkv,
                                                    float* __restrict__ wc) {
    const int row = blockIdx.x;
    const int c = threadIdx.x * 4;
    float4 v = *reinterpret_cast<const float4*>(&Wqkv[(size_t)row*TDc + 2*Dc + c]);
    *reinterpret_cast<float4*>(&wc[(size_t)row*LRW + 1024 + c]) = v;
}

// ---------------------------------------------------------------------------
// TF32 tensor-core GEMM, cp.async 2-stage pipeline.
// C[M,N] = A[M,K] @ B[K,N'] (ldb row stride for B; C row stride = N).
// 128x128 tile, BK=16, 256 threads, 2 CTAs/SM.
// ---------------------------------------------------------------------------
__global__ __launch_bounds__(256, 2) void gemm_tf32_kernel(const float* __restrict__ A,
                                                           const float* __restrict__ B,
                                                           float* __restrict__ C,
                                                           int M, int N, int K, int ldb) {
    __shared__ __align__(16) float As[2][128][20];   // 20.0 KB
    __shared__ __align__(16) float Bs[2][16][136];   // 17.4 KB

    const int tid = threadIdx.x;
    const int warp = tid >> 5, lane = tid & 31;
    const int g = lane >> 2, tig = lane & 3;
    const int wm = warp >> 2;
    const int wn = warp & 3;

    // per-thread copy assignments: 2 chunks of A, 2 chunks of B (16B each)
    const int c0 = tid * 2;
    const int aRow0 = c0 >> 2,       aKc0 = (c0 & 3) << 2;
    const int aRow1 = (c0+1) >> 2,   aKc1 = ((c0+1) & 3) << 2;
    const int bKr0 = c0 >> 5,        bNc0 = (c0 & 31) << 2;
    const int bKr1 = (c0+1) >> 5,    bNc1 = ((c0+1) & 31) << 2;

    const float* Ab = A + (size_t)blockIdx.y * 128 * K;
    const float* Bb = B + (size_t)blockIdx.x * 128;

    float acc[4][4][4];
#pragma unroll
    for (int i = 0; i < 4; i++)
#pragma unroll
        for (int j = 0; j < 4; j++)
#pragma unroll
            for (int e = 0; e < 4; e++) acc[i][j][e] = 0.f;

    const int nK = K >> 4;

    // prologue: stage 0
    cp16(&As[0][aRow0][aKc0], &Ab[(size_t)aRow0 * K + aKc0]);
    cp16(&As[0][aRow1][aKc1], &Ab[(size_t)aRow1 * K + aKc1]);
    cp16(&Bs[0][bKr0][bNc0], &Bb[(size_t)bKr0 * ldb + bNc0]);
    cp16(&Bs[0][bKr1][bNc1], &Bb[(size_t)bKr1 * ldb + bNc1]);
    cp_commit();

    int buf = 0;
    for (int kt = 0; kt < nK; kt++) {
        const bool more = (kt + 1 < nK);
        if (more) {
            const int k0 = (kt + 1) << 4;
            const int nb = buf ^ 1;
            cp16(&As[nb][aRow0][aKc0], &Ab[(size_t)aRow0 * K + k0 + aKc0]);
            cp16(&As[nb][aRow1][aKc1], &Ab[(size_t)aRow1 * K + k0 + aKc1]);
            cp16(&Bs[nb][bKr0][bNc0], &Bb[(size_t)(k0 + bKr0) * ldb + bNc0]);
            cp16(&Bs[nb][bKr1][bNc1], &Bb[(size_t)(k0 + bKr1) * ldb + bNc1]);
            cp_commit();
            cp_wait<1>();
        } else {
            cp_wait<0>();
        }
        __syncthreads();

#pragma unroll
        for (int ks = 0; ks < 16; ks += 8) {
            unsigned afr[4][4], bfr[4][2];
#pragma unroll
            for (int im = 0; im < 4; im++) {
                const int m0 = wm * 64 + im * 16;
                afr[im][0] = __float_as_uint(cvt_tf32(As[buf][m0 + g     ][ks + tig    ]));
                afr[im][1] = __float_as_uint(cvt_tf32(As[buf][m0 + g + 8 ][ks + tig    ]));
                afr[im][2] = __float_as_uint(cvt_tf32(As[buf][m0 + g     ][ks + tig + 4]));
                afr[im][3] = __float_as_uint(cvt_tf32(As[buf][m0 + g + 8 ][ks + tig + 4]));
            }
#pragma unroll
            for (int in_ = 0; in_ < 4; in_++) {
                const int n0 = wn * 32 + in_ * 8;
                bfr[in_][0] = __float_as_uint(cvt_tf32(Bs[buf][ks + tig    ][n0 + g]));
                bfr[in_][1] = __float_as_uint(cvt_tf32(Bs[buf][ks + tig + 4][n0 + g]));
            }
#pragma unroll
            for (int im = 0; im < 4; im++)
#pragma unroll
                for (int in_ = 0; in_ < 4; in_++)
                    mma_tf32(acc[im][in_], afr[im], bfr[in_]);
        }
        __syncthreads();
        buf ^= 1;
    }

#pragma unroll
    for (int im = 0; im < 4; im++) {
        const size_t row0 = (size_t)blockIdx.y * 128 + wm * 64 + im * 16 + g;
#pragma unroll
        for (int in_ = 0; in_ < 4; in_++) {
            const size_t col = (size_t)blockIdx.x * 128 + wn * 32 + in_ * 8 + tig * 2;
            float2 v0 = make_float2(acc[im][in_][0], acc[im][in_][1]);
            float2 v1 = make_float2(acc[im][in_][2], acc[im][in_][3]);
            *reinterpret_cast<float2*>(&C[row0 * N + col])       = v0;
            *reinterpret_cast<float2*>(&C[(row0 + 8) * N + col]) = v1;
        }
    }
}

// ---------------------------------------------------------------------------
// Tensor-core flash attention, 64-key tiles, 2 CTAs/SM, heavy-first schedule.
// ql at row+h*32, kl at row+512+h*32, v at row+1024+h*64 (all in g_lr, stride 2048).
// ---------------------------------------------------------------------------
#define KLS_STRIDE 36
#define VS_STRIDE  72
#define KT 64

__global__ __launch_bounds__(256, 2) void attn_tc_kernel(float* __restrict__ y) {
    __shared__ float kls[KT*KLS_STRIDE];
    __shared__ float vs [KT*VS_STRIDE];

    const int blk = blockIdx.x;
    const int qt = 15 - (blk & 15);        // heavy tiles first
    const int h  = (blk >> 4) & 15;
    const int b  = blk >> 8;
    const int tid  = threadIdx.x;
    const int warp = tid >> 5, lane = tid & 31;
    const int g = lane >> 2, tig = lane & 3;
    const int m0 = warp * 16;

    unsigned aq[4][4];
    {
        const float* qlp = g_lr + (size_t)(b*Tc + qt*128 + m0) * LRW + h*Rc;
#pragma unroll
        for (int ks = 0; ks < 4; ks++) {
            aq[ks][0] = __float_as_uint(cvt_tf32(qlp[(size_t)(g    )*LRW + ks*8 + tig    ]));
            aq[ks][1] = __float_as_uint(cvt_tf32(qlp[(size_t)(g + 8)*LRW + ks*8 + tig    ]));
            aq[ks][2] = __float_as_uint(cvt_tf32(qlp[(size_t)(g    )*LRW + ks*8 + tig + 4]));
            aq[ks][3] = __float_as_uint(cvt_tf32(qlp[(size_t)(g + 8)*LRW + ks*8 + tig + 4]));
        }
    }

    float of[8][4];
#pragma unroll
    for (int nt = 0; nt < 8; nt++)
#pragma unroll
        for (int e = 0; e < 4; e++) of[nt][e] = 0.f;
    float m0r = -1e30f, m1r = -1e30f, l0 = 0.f, l1 = 0.f;

    const float* klg = g_lr + (size_t)(b*Tc) * LRW + 512 + h*Rc;
    const float* vg  = g_lr + (size_t)(b*Tc) * LRW + 1024 + h*DHc;

    const unsigned srcA = (lane & ~3u) | (unsigned)(tig >> 1);
    const unsigned srcB = srcA + 2u;

    const int ktMax = 2*qt + 1;
    for (int kt = 0; kt <= ktMax; kt++) {
        if (kt) __syncthreads();
#pragma unroll
        for (int i = 0; i < 2; i++) {
            const int f = tid + i*256;
            const int key = f >> 3, r0 = (f & 7) << 2;
            float4 v = *reinterpret_cast<const float4*>(klg + (size_t)(kt*KT + key)*LRW + r0);
            float* dst = kls + key*KLS_STRIDE + r0;
            dst[0] = cvt_tf32(v.x); dst[1] = cvt_tf32(v.y);
            dst[2] = cvt_tf32(v.z); dst[3] = cvt_tf32(v.w);
        }
#pragma unroll
        for (int i = 0; i < 4; i++) {
            const int f = tid + i*256;
            const int key = f >> 4, j = (f & 15) << 2;
            float4 v = *reinterpret_cast<const float4*>(vg + (size_t)(kt*KT + key)*LRW + j);
            float* dst = vs + key*VS_STRIDE + j;
            dst[0] = cvt_tf32(v.x); dst[1] = cvt_tf32(v.y);
            dst[2] = cvt_tf32(v.z); dst[3] = cvt_tf32(v.w);
        }
        __syncthreads();

        const bool masked = (kt >= 2*qt);
        const int cbase = (kt - 2*qt) * KT;
        if (masked && (m0 + 15) < cbase) continue;

        float sf[8][4];
#pragma unroll
        for (int nt = 0; nt < 8; nt++) {
#pragma unroll
            for (int e = 0; e < 4; e++) sf[nt][e] = 0.f;
#pragma unroll
            for (int ks = 0; ks < 4; ks++) {
                unsigned bb[2];
                bb[0] = __float_as_uint(kls[(nt*8 + g)*KLS_STRIDE + ks*8 + tig    ]);
                bb[1] = __float_as_uint(kls[(nt*8 + g)*KLS_STRIDE + ks*8 + tig + 4]);
                mma_tf32(sf[nt], aq[ks], bb);
            }
        }

        if (masked) {
            const int r0l = m0 + g, r1l = r0l + 8;
#pragma unroll
            for (int nt = 0; nt < 8; nt++) {
                const int c = cbase + nt*8 + 2*tig;
                if (c     > r0l) sf[nt][0] = -1e30f;
                if (c + 1 > r0l) sf[nt][1] = -1e30f;
                if (c     > r1l) sf[nt][2] = -1e30f;
                if (c + 1 > r1l) sf[nt][3] = -1e30f;
            }
        }

        float mx0 = -1e30f, mx1 = -1e30f;
#pragma unroll
        for (int nt = 0; nt < 8; nt++) {
            mx0 = fmaxf(mx0, fmaxf(sf[nt][0], sf[nt][1]));
            mx1 = fmaxf(mx1, fmaxf(sf[nt][2], sf[nt][3]));
        }
        mx0 = fmaxf(mx0, __shfl_xor_sync(0xffffffffu, mx0, 1));
        mx0 = fmaxf(mx0, __shfl_xor_sync(0xffffffffu, mx0, 2));
        mx1 = fmaxf(mx1, __shfl_xor_sync(0xffffffffu, mx1, 1));
        mx1 = fmaxf(mx1, __shfl_xor_sync(0xffffffffu, mx1, 2));

        const float nm0 = fmaxf(m0r, mx0), nm1 = fmaxf(m1r, mx1);
        const float cor0 = __expf(m0r - nm0), cor1 = __expf(m1r - nm1);
        m0r = nm0; m1r = nm1;
        l0 *= cor0; l1 *= cor1;
#pragma unroll
        for (int nt = 0; nt < 8; nt++) {
            of[nt][0] *= cor0; of[nt][1] *= cor0;
            of[nt][2] *= cor1; of[nt][3] *= cor1;
        }

#pragma unroll
        for (int nt = 0; nt < 8; nt++) {
            float p0 = cvt_tf32(__expf(sf[nt][0] - m0r));
            float p1 = cvt_tf32(__expf(sf[nt][1] - m0r));
            float p2 = cvt_tf32(__expf(sf[nt][2] - m1r));
            float p3 = cvt_tf32(__expf(sf[nt][3] - m1r));
            sf[nt][0] = p0; sf[nt][1] = p1; sf[nt][2] = p2; sf[nt][3] = p3;
            l0 += p0 + p1; l1 += p2 + p3;
        }

#pragma unroll
        for (int kk = 0; kk < 8; kk++) {
            const float x0 = __shfl_sync(0xffffffffu, sf[kk][0], srcA);
            const float x1 = __shfl_sync(0xffffffffu, sf[kk][1], srcA);
            const float x2 = __shfl_sync(0xffffffffu, sf[kk][2], srcA);
            const float x3 = __shfl_sync(0xffffffffu, sf[kk][3], srcA);
            const float z0 = __shfl_sync(0xffffffffu, sf[kk][0], srcB);
            const float z1 = __shfl_sync(0xffffffffu, sf[kk][1], srcB);
            const float z2 = __shfl_sync(0xffffffffu, sf[kk][2], srcB);
            const float z3 = __shfl_sync(0xffffffffu, sf[kk][3], srcB);
            unsigned a[4];
            a[0] = __float_as_uint((tig & 1) ? x1 : x0);
            a[1] = __float_as_uint((tig & 1) ? x3 : x2);
            a[2] = __float_as_uint((tig & 1) ? z1 : z0);
            a[3] = __float_as_uint((tig & 1) ? z3 : z2);
#pragma unroll
            for (int nt = 0; nt < 8; nt++) {
                unsigned bb[2];
                bb[0] = __float_as_uint(vs[(kk*8 + tig    )*VS_STRIDE + nt*8 + g]);
                bb[1] = __float_as_uint(vs[(kk*8 + tig + 4)*VS_STRIDE + nt*8 + g]);
                mma_tf32(of[nt], a, bb);
            }
        }
    }

    l0 += __shfl_xor_sync(0xffffffffu, l0, 1);
    l0 += __shfl_xor_sync(0xffffffffu, l0, 2);
    l1 += __shfl_xor_sync(0xffffffffu, l1, 1);
    l1 += __shfl_xor_sync(0xffffffffu, l1, 2);
    const float inv0 = 1.f / l0, inv1 = 1.f / l1;

    float* yr0 = y + (size_t)(b*Tc + qt*128 + m0 + g) * Dc + h*DHc;
    float* yr1 = yr0 + (size_t)8 * Dc;
#pragma unroll
    for (int nt = 0; nt < 8; nt++) {
        float2 v0 = make_float2(of[nt][0]*inv0, of[nt][1]*inv0);
        float2 v1 = make_float2(of[nt][2]*inv1, of[nt][3]*inv1);
        *reinterpret_cast<float2*>(yr0 + nt*8 + 2*tig) = v0;
        *reinterpret_cast<float2*>(yr1 + nt*8 + 2*tig) = v1;
    }
}

extern "C" void kernel_launch(void* const* d_in, const int* in_sizes, int n_in,
                              void* d_out, int out_size) {
    const float* x      = (const float*)d_in[0];
    const float* W_qkv  = (const float*)d_in[1];
    const float* W_qlsr = (const float*)d_in[2];
    const float* W_klsr = (const float*)d_in[3];
    const float* core   = (const float*)d_in[4];
    const float* W_o    = (const float*)d_in[5];
    float* out = (float*)d_out;

    float* d_wc; cudaGetSymbolAddress((void**)&d_wc, g_wc);
    float* d_lr; cudaGetSymbolAddress((void**)&d_lr, g_lr);
    float* d_y;  cudaGetSymbolAddress((void**)&d_y,  g_y);

    // 0) fold LSR weights into wc[:, 0:1024); copy V weights into wc[:, 1024:2048)
    prep_kernel<<<dim3(8, 16), 256>>>(W_qkv, W_qlsr, W_klsr, core, d_wc);
    copyv_kernel<<<Dc, 256>>>(W_qkv, d_wc);

    // 1) [ql|kl|v] = x @ wc   (4096 x 2048 x 1024), cp.async tf32 GEMM
    gemm_tf32_kernel<<<dim3(LRW/128, Mrows/128), 256>>>(x, d_wc, d_lr, Mrows, LRW, Dc, LRW);

    // 2) causal flash attention (tensor cores, 64-key tiles) -> g_y
    attn_tc_kernel<<<Bc*Hc*(Tc/128), 256>>>(d_y);

    // 3) out = y @ W_o  (4096 x 1024 x 1024)
    gemm_tf32_kernel<<<dim3(Dc/128, Mrows/128), 256>>>(d_y, W_o, out, Mrows, Dc, Dc, Dc);
}